// round 7
// baseline (speedup 1.0000x reference)
#include <cuda_runtime.h>
#include <math.h>
#include <stdint.h>

#define BATCH 2
#define T 2048
#define DM 1024
#define NH 16
#define DK 64
#define RR 8
#define LORA_SCALE 2.0f
#define MTOT (BATCH*T)      // 4096

// ---------------- scratch ----------------
__device__ float g_weff[3][DM*DM];
__device__ float g_wo[DM*DM];
__device__ float g_qkv[3][BATCH*NH*T*DK];
__device__ float g_attn[MTOT*DM];
__device__ int   g_anyzero;

// ---------------- helpers ----------------
__device__ __forceinline__ float tf32r(float x) {
    uint32_t r;
    asm("cvt.rna.tf32.f32 %0, %1;" : "=r"(r) : "f"(x));
    return __uint_as_float(r);
}
__device__ __forceinline__ uint32_t tf32r_u(float x) {
    uint32_t r;
    asm("cvt.rna.tf32.f32 %0, %1;" : "=r"(r) : "f"(x));
    return r;
}
#define CP_ASYNC16(dst, src) \
    asm volatile("cp.async.cg.shared.global [%0], [%1], 16;" :: "r"(dst), "l"(src))
#define CP_COMMIT() asm volatile("cp.async.commit_group;" ::: "memory")
#define CP_WAIT(n)  asm volatile("cp.async.wait_group %0;" :: "n"(n) : "memory")

__device__ __forceinline__ uint32_t smem_u32(const void* p) {
    uint32_t a;
    asm("{ .reg .u64 t; cvta.to.shared.u64 t, %1; cvt.u32.u64 %0, t; }" : "=r"(a) : "l"(p));
    return a;
}
__device__ __forceinline__ void mma_tf32(float* c, const uint32_t* a, const uint32_t* b) {
    asm volatile(
        "mma.sync.aligned.m16n8k8.row.col.f32.tf32.tf32.f32 "
        "{%0,%1,%2,%3}, {%4,%5,%6,%7}, {%8,%9}, {%0,%1,%2,%3};"
        : "+f"(c[0]), "+f"(c[1]), "+f"(c[2]), "+f"(c[3])
        : "r"(a[0]), "r"(a[1]), "r"(a[2]), "r"(a[3]), "r"(b[0]), "r"(b[1]));
}
__device__ __forceinline__ void mma_tf32b(float* c, const uint32_t* a,
                                          uint32_t b0, uint32_t b1) {
    asm volatile(
        "mma.sync.aligned.m16n8k8.row.col.f32.tf32.tf32.f32 "
        "{%0,%1,%2,%3}, {%4,%5,%6,%7}, {%8,%9}, {%0,%1,%2,%3};"
        : "+f"(c[0]), "+f"(c[1]), "+f"(c[2]), "+f"(c[3])
        : "r"(a[0]), "r"(a[1]), "r"(a[2]), "r"(a[3]), "r"(b0), "r"(b1));
}

// ---------------- mask scan ----------------
__global__ void maskscan_init() { g_anyzero = 0; }
__global__ void maskscan(const int* __restrict__ mask, int n) {
    int i = blockIdx.x * 256 + threadIdx.x;
    int z = 0;
    for (int k = i; k < n; k += gridDim.x * 256) z |= (mask[k] == 0);
    if (__any_sync(0xffffffffu, z) && (threadIdx.x & 31) == 0)
        atomicOr(&g_anyzero, 1);
}

// ---------------- fused prep: weff q/k/v (z=0..2) + Wo round (z=3) ----------
__global__ void prep_kernel(const float* __restrict__ Wq, const float* __restrict__ Aq,
                            const float* __restrict__ Bq,
                            const float* __restrict__ Wk, const float* __restrict__ Ak,
                            const float* __restrict__ Bk,
                            const float* __restrict__ Wv, const float* __restrict__ Av,
                            const float* __restrict__ Bv,
                            const float* __restrict__ Wo,
                            float* __restrict__ weff, float* __restrict__ wo) {
    const int z = blockIdx.y;
    int idx = blockIdx.x * 256 + threadIdx.x;
    if (z == 3) {
        wo[idx] = tf32r(Wo[idx]);
        return;
    }
    const float* W = (z == 0) ? Wq : (z == 1) ? Wk : Wv;
    const float* A = (z == 0) ? Aq : (z == 1) ? Ak : Av;
    const float* B = (z == 0) ? Bq : (z == 1) ? Bk : Bv;
    int o = idx >> 10;
    int d = idx & 1023;
    float s = 0.f;
#pragma unroll
    for (int r = 0; r < RR; r++) s += B[o*RR + r] * A[r*DM + d];
    weff[(size_t)z*DM*DM + idx] = tf32r(W[idx] + LORA_SCALE * s);
}

// ---------------- persistent mma.sync tf32 GEMM ------------------------------
// C[m,n] = sum_k A[m,k]*W[n,k] + bias[n]. W pre-rounded; A rounded in-register.
// CTA 128x128, 8 warps (2M x 4N), warp tile 64x32, KT=32, 3-stage, 1 sync/iter.
// Persistent: CTA loops tiles with stride gridDim.x over ntiles (256 per z).
#define KT 32
#define NIT (DM / KT)          // 32
#define SROW 36
#define STG_F (128 * SROW)
#define GEMM_SMEM (3 * 2 * STG_F * 4)   // 110592 B

__global__ __launch_bounds__(256, 2)
void gemm_mma(const float* __restrict__ A0, const float* __restrict__ A1,
              const float* __restrict__ A2,
              const float* __restrict__ W0, const float* __restrict__ W1,
              const float* __restrict__ W2,
              const float* __restrict__ b0, const float* __restrict__ b1,
              const float* __restrict__ b2,
              float* __restrict__ C0, float* __restrict__ C1,
              float* __restrict__ C2, int ntiles, int mode) {
    extern __shared__ float smp[];
    const int tid = threadIdx.x;
    const int wid = tid >> 5;
    const int lane = tid & 31;
    const int wm = wid >> 2;
    const int wn = wid & 3;
    const uint32_t sbase = smem_u32(smp);
    const int arow_l = wm * 64 + (lane >> 2);
    const int bcol_l = wn * 32 + (lane >> 2);
    const int kq = lane & 3;

    for (int tile = blockIdx.x; tile < ntiles; tile += gridDim.x) {
        const int z = tile >> 8;
        const int rem = tile & 255;
        const int col0 = (rem & 7) * 128;
        const int row0 = (rem >> 3) * 128;
        const float* A   = (z == 0) ? A0 : (z == 1) ? A1 : A2;
        const float* W   = (z == 0) ? W0 : (z == 1) ? W1 : W2;
        const float* bia = (z == 0) ? b0 : (z == 1) ? b1 : b2;
        float*       C   = (z == 0) ? C0 : (z == 1) ? C1 : C2;

        // protect prev tile's stage reads before overwriting
        __syncthreads();

        float acc[4][4][4];
#pragma unroll
        for (int i = 0; i < 4; i++)
#pragma unroll
            for (int j = 0; j < 4; j++)
#pragma unroll
                for (int r = 0; r < 4; r++) acc[i][j][r] = 0.f;

        auto load_stage = [&](int g) {
            const int st = g % 3;
            const int k0 = g * KT;
            const uint32_t abase = sbase + (uint32_t)st * (2*STG_F*4);
            const uint32_t bbase = abase + STG_F*4;
#pragma unroll
            for (int i = 0; i < 4; i++) {
                int e = tid + i * 256;
                int r = e >> 3;
                int c4 = (e & 7) * 4;
                uint32_t doff = (uint32_t)(r * SROW + c4) * 4;
                CP_ASYNC16(abase + doff, A + (size_t)(row0 + r) * DM + k0 + c4);
                CP_ASYNC16(bbase + doff, W + (size_t)(col0 + r) * DM + k0 + c4);
            }
            CP_COMMIT();
        };

        load_stage(0);
        load_stage(1);

        for (int it = 0; it < NIT; it++) {
            if (it + 1 < NIT) { CP_WAIT(1); } else { CP_WAIT(0); }
            __syncthreads();
            if (it + 2 < NIT) load_stage(it + 2);

            const float* as = smp + (it % 3) * (2*STG_F);
            const float* bs = as + STG_F;
#pragma unroll
            for (int ks = 0; ks < KT; ks += 8) {
                uint32_t af[4][4];
#pragma unroll
                for (int mi = 0; mi < 4; mi++) {
                    int rr = arow_l + mi * 16;
                    af[mi][0] = tf32r_u(as[(rr     ) * SROW + ks + kq    ]);
                    af[mi][1] = tf32r_u(as[(rr +  8) * SROW + ks + kq    ]);
                    af[mi][2] = tf32r_u(as[(rr     ) * SROW + ks + kq + 4]);
                    af[mi][3] = tf32r_u(as[(rr +  8) * SROW + ks + kq + 4]);
                }
                uint32_t bf[4][2];
#pragma unroll
                for (int ni = 0; ni < 4; ni++) {
                    int cc = bcol_l + ni * 8;
                    bf[ni][0] = __float_as_uint(bs[cc * SROW + ks + kq    ]);
                    bf[ni][1] = __float_as_uint(bs[cc * SROW + ks + kq + 4]);
                }
#pragma unroll
                for (int mi = 0; mi < 4; mi++)
#pragma unroll
                    for (int ni = 0; ni < 4; ni++)
                        mma_tf32(acc[mi][ni], af[mi], bf[ni]);
            }
        }

#pragma unroll
        for (int mi = 0; mi < 4; mi++) {
            const int r_lo = row0 + wm * 64 + mi * 16 + (lane >> 2);
            const int r_hi = r_lo + 8;
#pragma unroll
            for (int ni = 0; ni < 4; ni++) {
                const int n = col0 + wn * 32 + ni * 8 + (lane & 3) * 2;
                const float2 bv = *(const float2*)(bia + n);
                float2 lo = make_float2(acc[mi][ni][0] + bv.x, acc[mi][ni][1] + bv.y);
                float2 hi = make_float2(acc[mi][ni][2] + bv.x, acc[mi][ni][3] + bv.y);
                if (mode == 0) {
                    *(float2*)(C + (size_t)r_lo * DM + n) = lo;
                    *(float2*)(C + (size_t)r_hi * DM + n) = hi;
                } else {
                    lo.x = tf32r(lo.x); lo.y = tf32r(lo.y);
                    hi.x = tf32r(hi.x); hi.y = tf32r(hi.y);
                    const int h = n >> 6, dk = n & (DK - 1);
                    {
                        int bb = r_lo >> 11, t = r_lo & (T - 1);
                        *(float2*)(C + (((size_t)(bb*NH + h))*T + t)*DK + dk) = lo;
                    }
                    {
                        int bb = r_hi >> 11, t = r_hi & (T - 1);
                        *(float2*)(C + (((size_t)(bb*NH + h))*T + t)*DK + dk) = hi;
                    }
                }
            }
        }
    }
}

// ---------------- tensor-core flash attention, 3-stage KV ring ---------------
#define KSTRIDE 68
#define VSTRIDE 72
#define KBYTES 17408
#define BUFBYTES 35840
#define FA_SMEM (3*BUFBYTES)    // 107520
#define NT_TILES (T/64)         // 32

__global__ __launch_bounds__(256, 2)
void flash_mma(const float* __restrict__ Q, const float* __restrict__ K,
               const float* __restrict__ V, const int* __restrict__ mask,
               float* __restrict__ O) {
    extern __shared__ float pool[];
    const int tid = threadIdx.x, wid = tid >> 5, lane = tid & 31;
    const int qt = blockIdx.x, h = blockIdx.y, b = blockIdx.z;
    const int bh = b*NH + h;
    const int r = lane >> 2, qd = lane & 3;
    const int anyz = g_anyzero;
    const uint32_t pbase = smem_u32(pool);

    // ---- stage Q (into stage-0 region), build fragments, then release ----
    {
        const float* Qg = Q + ((size_t)bh*T + (size_t)qt*128)*DK;
#pragma unroll
        for (int i = 0; i < 8; i++) {
            int e = tid + i*256;
            int row = e >> 4, c4 = (e & 15) * 4;
            CP_ASYNC16(pbase + row*(KSTRIDE*4) + c4*4, Qg + row*64 + c4);
        }
        CP_COMMIT(); CP_WAIT(0);
    }
    __syncthreads();
    uint32_t qf[8][4];
    {
        const int r0 = wid*16 + r;
#pragma unroll
        for (int ks = 0; ks < 8; ks++) {
            qf[ks][0] = __float_as_uint(pool[(r0    )*KSTRIDE + ks*8 + qd    ] * 0.125f);
            qf[ks][1] = __float_as_uint(pool[(r0 + 8)*KSTRIDE + ks*8 + qd    ] * 0.125f);
            qf[ks][2] = __float_as_uint(pool[(r0    )*KSTRIDE + ks*8 + qd + 4] * 0.125f);
            qf[ks][3] = __float_as_uint(pool[(r0 + 8)*KSTRIDE + ks*8 + qd + 4] * 0.125f);
        }
    }
    __syncthreads();

    const float* Kg = K + (size_t)bh*T*DK;
    const float* Vg = V + (size_t)bh*T*DK;

    auto loadKV = [&](int kt) {
        const float* kg = Kg + (size_t)kt*64*DK;
        const float* vg = Vg + (size_t)kt*64*DK;
        uint32_t kb = pbase + (uint32_t)(kt % 3) * BUFBYTES;
        uint32_t vb = kb + KBYTES;
#pragma unroll
        for (int i = 0; i < 4; i++) {
            int e = tid + i*256;
            int row = e >> 4, c4 = (e & 15) * 4;
            CP_ASYNC16(kb + row*(KSTRIDE*4) + c4*4, kg + row*64 + c4);
            CP_ASYNC16(vb + row*(VSTRIDE*4) + c4*4, vg + row*64 + c4);
        }
        CP_COMMIT();
    };

    float m_lo = -1e30f, m_hi = -1e30f, l_lo = 0.f, l_hi = 0.f;
    float oacc[8][4];
#pragma unroll
    for (int i = 0; i < 8; i++)
#pragma unroll
        for (int j = 0; j < 4; j++) oacc[i][j] = 0.f;

    const int q0 = qt*128 + wid*16;
    const int s1 = (lane & 28) | (qd >> 1);
    const int s2 = s1 + 2;
    const bool odd = (qd & 1) != 0;

    loadKV(0);
    loadKV(1);

    for (int kt = 0; kt < NT_TILES; kt++) {
        if (kt + 1 < NT_TILES) { CP_WAIT(1); } else { CP_WAIT(0); }
        __syncthreads();
        if (kt + 2 < NT_TILES) loadKV(kt + 2);

        const float* ksm = pool + (kt % 3) * (BUFBYTES/4);
        const float* vsm = ksm + (KBYTES/4);

        float sa[8][4];
#pragma unroll
        for (int i = 0; i < 8; i++)
#pragma unroll
            for (int j = 0; j < 4; j++) sa[i][j] = 0.f;
#pragma unroll
        for (int ks = 0; ks < 8; ks++) {
#pragma unroll
            for (int nt = 0; nt < 8; nt++) {
                uint32_t b0 = __float_as_uint(ksm[(nt*8 + r)*KSTRIDE + ks*8 + qd    ]);
                uint32_t b1 = __float_as_uint(ksm[(nt*8 + r)*KSTRIDE + ks*8 + qd + 4]);
                mma_tf32b(sa[nt], qf[ks], b0, b1);
            }
        }

        if (anyz) {
#pragma unroll
            for (int nt = 0; nt < 8; nt++) {
                const int col = kt*64 + nt*8 + qd*2;
                int2 mlo = *(const int2*)(mask + (size_t)(q0 + r    )*T + col);
                int2 mhi = *(const int2*)(mask + (size_t)(q0 + r + 8)*T + col);
                if (mlo.x == 0) sa[nt][0] = -1e9f;
                if (mlo.y == 0) sa[nt][1] = -1e9f;
                if (mhi.x == 0) sa[nt][2] = -1e9f;
                if (mhi.y == 0) sa[nt][3] = -1e9f;
            }
        }

        float tm_lo = m_lo, tm_hi = m_hi;
#pragma unroll
        for (int nt = 0; nt < 8; nt++) {
            tm_lo = fmaxf(tm_lo, fmaxf(sa[nt][0], sa[nt][1]));
            tm_hi = fmaxf(tm_hi, fmaxf(sa[nt][2], sa[nt][3]));
        }
        tm_lo = fmaxf(tm_lo, __shfl_xor_sync(0xffffffffu, tm_lo, 1));
        tm_lo = fmaxf(tm_lo, __shfl_xor_sync(0xffffffffu, tm_lo, 2));
        tm_hi = fmaxf(tm_hi, __shfl_xor_sync(0xffffffffu, tm_hi, 1));
        tm_hi = fmaxf(tm_hi, __shfl_xor_sync(0xffffffffu, tm_hi, 2));
        const float corr_lo = __expf(m_lo - tm_lo);
        const float corr_hi = __expf(m_hi - tm_hi);
        m_lo = tm_lo; m_hi = tm_hi;

        float suml_lo = 0.f, suml_hi = 0.f;
#pragma unroll
        for (int nt = 0; nt < 8; nt++) {
            sa[nt][0] = __expf(sa[nt][0] - m_lo);
            sa[nt][1] = __expf(sa[nt][1] - m_lo);
            sa[nt][2] = __expf(sa[nt][2] - m_hi);
            sa[nt][3] = __expf(sa[nt][3] - m_hi);
            suml_lo += sa[nt][0] + sa[nt][1];
            suml_hi += sa[nt][2] + sa[nt][3];
        }
        suml_lo += __shfl_xor_sync(0xffffffffu, suml_lo, 1);
        suml_lo += __shfl_xor_sync(0xffffffffu, suml_lo, 2);
        suml_hi += __shfl_xor_sync(0xffffffffu, suml_hi, 1);
        suml_hi += __shfl_xor_sync(0xffffffffu, suml_hi, 2);
        l_lo = l_lo * corr_lo + suml_lo;
        l_hi = l_hi * corr_hi + suml_hi;
#pragma unroll
        for (int nt = 0; nt < 8; nt++) {
            oacc[nt][0] *= corr_lo; oacc[nt][1] *= corr_lo;
            oacc[nt][2] *= corr_hi; oacc[nt][3] *= corr_hi;
        }

#pragma unroll
        for (int j = 0; j < 8; j++) {
            float x0 = __shfl_sync(0xffffffffu, sa[j][0], s1);
            float x1 = __shfl_sync(0xffffffffu, sa[j][1], s1);
            float x2 = __shfl_sync(0xffffffffu, sa[j][2], s1);
            float x3 = __shfl_sync(0xffffffffu, sa[j][3], s1);
            float y0 = __shfl_sync(0xffffffffu, sa[j][0], s2);
            float y1 = __shfl_sync(0xffffffffu, sa[j][1], s2);
            float y2 = __shfl_sync(0xffffffffu, sa[j][2], s2);
            float y3 = __shfl_sync(0xffffffffu, sa[j][3], s2);
            uint32_t af[4];
            af[0] = tf32r_u(odd ? x1 : x0);
            af[1] = tf32r_u(odd ? x3 : x2);
            af[2] = tf32r_u(odd ? y1 : y0);
            af[3] = tf32r_u(odd ? y3 : y2);
#pragma unroll
            for (int nt = 0; nt < 8; nt++) {
                uint32_t b0 = __float_as_uint(vsm[(j*8 + qd    )*VSTRIDE + nt*8 + r]);
                uint32_t b1 = __float_as_uint(vsm[(j*8 + qd + 4)*VSTRIDE + nt*8 + r]);
                mma_tf32b(oacc[nt], af, b0, b1);
            }
        }
    }

    const float ilo = 1.f / l_lo;
    const float ihi = 1.f / l_hi;
#pragma unroll
    for (int nt = 0; nt < 8; nt++) {
        const int col = h*64 + nt*8 + qd*2;
        float2 lo = make_float2(tf32r(oacc[nt][0]*ilo), tf32r(oacc[nt][1]*ilo));
        float2 hi = make_float2(tf32r(oacc[nt][2]*ihi), tf32r(oacc[nt][3]*ihi));
        *(float2*)(O + (size_t)(b*T + q0 + r    )*DM + col) = lo;
        *(float2*)(O + (size_t)(b*T + q0 + r + 8)*DM + col) = hi;
    }
}

// ---------------- launch ----------------
extern "C" void kernel_launch(void* const* d_in, const int* in_sizes, int n_in,
                              void* d_out, int out_size) {
    const float* q    = (const float*)d_in[0];
    const float* k    = (const float*)d_in[1];
    const float* v    = (const float*)d_in[2];
    const int*   mask = (const int*)  d_in[3];
    const float* Wq = (const float*)d_in[4],  *bq = (const float*)d_in[5];
    const float* Aq = (const float*)d_in[6],  *Bq = (const float*)d_in[7];
    const float* Wk = (const float*)d_in[8],  *bk = (const float*)d_in[9];
    const float* Ak = (const float*)d_in[10], *Bk = (const float*)d_in[11];
    const float* Wv = (const float*)d_in[12], *bv = (const float*)d_in[13];
    const float* Av = (const float*)d_in[14], *Bv = (const float*)d_in[15];
    const float* Wo = (const float*)d_in[16], *bo = (const float*)d_in[17];
    float* out = (float*)d_out;

    float *weff, *wo, *qkv, *attn;
    cudaGetSymbolAddress((void**)&weff, g_weff);
    cudaGetSymbolAddress((void**)&wo,   g_wo);
    cudaGetSymbolAddress((void**)&qkv,  g_qkv);
    cudaGetSymbolAddress((void**)&attn, g_attn);

    float* weffq = weff;
    float* weffk = weff + (size_t)DM*DM;
    float* weffv = weff + (size_t)2*DM*DM;
    const size_t QKV_SZ = (size_t)BATCH*NH*T*DK;
    float* Qp = qkv;
    float* Kp = qkv + QKV_SZ;
    float* Vp = qkv + 2*QKV_SZ;

    cudaFuncSetAttribute(gemm_mma, cudaFuncAttributeMaxDynamicSharedMemorySize, GEMM_SMEM);
    cudaFuncSetAttribute(flash_mma, cudaFuncAttributeMaxDynamicSharedMemorySize, FA_SMEM);

    prep_kernel<<<dim3(DM*DM/256, 4), 256>>>(Wq, Aq, Bq, Wk, Ak, Bk, Wv, Av, Bv,
                                             Wo, weff, wo);
    maskscan_init<<<1, 1>>>();
    maskscan<<<4096, 256>>>(mask, T*T);

    // persistent batched QKV GEMM: 768 tiles over 296 CTAs
    gemm_mma<<<296, 256, GEMM_SMEM>>>(q, k, v, weffq, weffk, weffv,
                                      bq, bk, bv, Qp, Kp, Vp, 768, 1);

    flash_mma<<<dim3(T/128, NH, BATCH), 256, FA_SMEM>>>(Qp, Kp, Vp, mask, attn);

    gemm_mma<<<256, 256, GEMM_SMEM>>>(attn, attn, attn, wo, wo, wo,
                                      bo, bo, bo, out, out, out, 256, 0);
}

// round 8
// speedup vs baseline: 1.9299x; 1.9299x over previous
#include <cuda_runtime.h>
#include <cuda_fp16.h>
#include <math.h>
#include <stdint.h>

#define BATCH 2
#define T 2048
#define DM 1024
#define NH 16
#define DK 64
#define RR 8
#define LORA_SCALE 2.0f
#define MTOT (BATCH*T)      // 4096

// ---------------- scratch ----------------
__device__ __half g_weffh[3][DM*DM];          // folded LoRA weights, fp16
__device__ __half g_woh[DM*DM];               // Wo fp16
__device__ __half g_acth[3][MTOT*DM];         // q,k,v activations fp16
__device__ __half g_q[BATCH*NH*T*DK];         // Q (b,h,t,d) fp16, pre-scaled 1/8
__device__ __half g_k[BATCH*NH*T*DK];         // K (b,h,t,d) fp16
__device__ __half g_vt[BATCH*NH*DK*T];        // V transposed (b,h,d,t) fp16
__device__ __half g_attnh[MTOT*DM];           // attention out fp16
__device__ int    g_anyzero;

// ---------------- helpers ----------------
#define CP_ASYNC16(dst, src) \
    asm volatile("cp.async.cg.shared.global [%0], [%1], 16;" :: "r"(dst), "l"(src))
#define CP_COMMIT() asm volatile("cp.async.commit_group;" ::: "memory")
#define CP_WAIT(n)  asm volatile("cp.async.wait_group %0;" :: "n"(n) : "memory")

__device__ __forceinline__ uint32_t smem_u32(const void* p) {
    uint32_t a;
    asm("{ .reg .u64 t; cvta.to.shared.u64 t, %1; cvt.u32.u64 %0, t; }" : "=r"(a) : "l"(p));
    return a;
}
__device__ __forceinline__ uint32_t packh2(float a, float b) {
    __half2 h = __floats2half2_rn(a, b);
    return *(uint32_t*)&h;
}
__device__ __forceinline__ void mma16816(float* c, const uint32_t* a,
                                         uint32_t b0, uint32_t b1) {
    asm volatile(
        "mma.sync.aligned.m16n8k16.row.col.f32.f16.f16.f32 "
        "{%0,%1,%2,%3}, {%4,%5,%6,%7}, {%8,%9}, {%0,%1,%2,%3};"
        : "+f"(c[0]), "+f"(c[1]), "+f"(c[2]), "+f"(c[3])
        : "r"(a[0]), "r"(a[1]), "r"(a[2]), "r"(a[3]), "r"(b0), "r"(b1));
}

// ---------------- mask scan ----------------
__global__ void maskscan_init() { g_anyzero = 0; }
__global__ void maskscan(const int* __restrict__ mask, int n) {
    int i = blockIdx.x * 256 + threadIdx.x;
    int z = 0;
    for (int k = i; k < n; k += gridDim.x * 256) z |= (mask[k] == 0);
    if (__any_sync(0xffffffffu, z) && (threadIdx.x & 31) == 0)
        atomicOr(&g_anyzero, 1);
}

// ---------------- prep: weff q/k/v (z=0..2) fp16 + Wo fp16 (z=3) ------------
__global__ void prep_kernel(const float* __restrict__ Wq, const float* __restrict__ Aq,
                            const float* __restrict__ Bq,
                            const float* __restrict__ Wk, const float* __restrict__ Ak,
                            const float* __restrict__ Bk,
                            const float* __restrict__ Wv, const float* __restrict__ Av,
                            const float* __restrict__ Bv,
                            const float* __restrict__ Wo,
                            __half* __restrict__ weff, __half* __restrict__ wo) {
    const int z = blockIdx.y;
    int idx = blockIdx.x * 256 + threadIdx.x;
    if (z == 3) {
        wo[idx] = __float2half_rn(Wo[idx]);
        return;
    }
    const float* W = (z == 0) ? Wq : (z == 1) ? Wk : Wv;
    const float* A = (z == 0) ? Aq : (z == 1) ? Ak : Av;
    const float* B = (z == 0) ? Bq : (z == 1) ? Bk : Bv;
    int o = idx >> 10;
    int d = idx & 1023;
    float s = 0.f;
#pragma unroll
    for (int r = 0; r < RR; r++) s += B[o*RR + r] * A[r*DM + d];
    weff[(size_t)z*DM*DM + idx] = __float2half_rn(W[idx] + LORA_SCALE * s);
}

// ---------------- activations fp32 -> fp16 ----------------
__global__ void act_half(const float* __restrict__ q, const float* __restrict__ k,
                         const float* __restrict__ v, __half* __restrict__ out) {
    const int z = blockIdx.y;
    const float* src = (z == 0) ? q : (z == 1) ? k : v;
    int i = blockIdx.x * 256 + threadIdx.x;       // per 8 elems
    float4 a = ((const float4*)src)[i*2];
    float4 b = ((const float4*)src)[i*2 + 1];
    uint4 o;
    o.x = packh2(a.x, a.y); o.y = packh2(a.z, a.w);
    o.z = packh2(b.x, b.y); o.w = packh2(b.z, b.w);
    ((uint4*)(out + (size_t)z*MTOT*DM))[i] = o;
}

// ---------------- fp16 mma GEMM: C[m,n] = sum_k A[m,k]*W[n,k] + bias[n] ------
// CTA 128x128, 8 warps (2M x 4N), warp tile 64x32, KT=64 halves, 3-stage.
// mode 0: C fp32 plain. mode 1: z=0 -> Q half scaled 1/8; z=1 -> K half;
//                               z=2 -> V half TRANSPOSED (b,h,d,t).
#define KT 64
#define NIT (DM / KT)          // 16
#define SROWH 72               // halves per row (64 + 8 pad)
#define STG_H (128 * SROWH)    // halves per operand per stage
#define GEMM_SMEM (3 * 2 * STG_H * 2)   // 110592 B

__global__ __launch_bounds__(256, 2)
void gemm_h(const __half* __restrict__ A0, const __half* __restrict__ A1,
            const __half* __restrict__ A2,
            const __half* __restrict__ W0, const __half* __restrict__ W1,
            const __half* __restrict__ W2,
            const float* __restrict__ b0, const float* __restrict__ b1,
            const float* __restrict__ b2,
            void* __restrict__ C0, void* __restrict__ C1,
            void* __restrict__ C2, int mode) {
    extern __shared__ __half smh[];
    const int z = blockIdx.z;
    const __half* A   = (z == 0) ? A0 : (z == 1) ? A1 : A2;
    const __half* W   = (z == 0) ? W0 : (z == 1) ? W1 : W2;
    const float*  bia = (z == 0) ? b0 : (z == 1) ? b1 : b2;
    void*         C   = (z == 0) ? C0 : (z == 1) ? C1 : C2;

    const int tid = threadIdx.x;
    const int wid = tid >> 5;
    const int lane = tid & 31;
    const int wm = wid >> 2;
    const int wn = wid & 3;
    const int row0 = blockIdx.y * 128;
    const int col0 = blockIdx.x * 128;
    const uint32_t sbase = smem_u32(smh);

    float acc[4][4][4];
#pragma unroll
    for (int i = 0; i < 4; i++)
#pragma unroll
        for (int j = 0; j < 4; j++)
#pragma unroll
            for (int r = 0; r < 4; r++) acc[i][j][r] = 0.f;

    // stage: per operand 128 rows x 64 halves = 1024 chunks of 16B; 4/thread
    auto load_stage = [&](int g) {
        const int st = g % 3;
        const int k0 = g * KT;
        const uint32_t abase = sbase + (uint32_t)st * (2*STG_H*2);
        const uint32_t bbase = abase + STG_H*2;
#pragma unroll
        for (int i = 0; i < 4; i++) {
            int e = tid + i * 256;          // 0..1023
            int r = e >> 3;                 // 0..127
            int c8 = (e & 7) * 8;           // half offset 0..56
            uint32_t doff = (uint32_t)(r * SROWH + c8) * 2;
            CP_ASYNC16(abase + doff, A + (size_t)(row0 + r) * DM + k0 + c8);
            CP_ASYNC16(bbase + doff, W + (size_t)(col0 + r) * DM + k0 + c8);
        }
        CP_COMMIT();
    };

    load_stage(0);
    load_stage(1);

    const int arow = wm * 64 + (lane >> 2);
    const int bcol = wn * 32 + (lane >> 2);
    const int kq2 = (lane & 3) * 2;

    for (int it = 0; it < NIT; it++) {
        if (it + 1 < NIT) { CP_WAIT(1); } else { CP_WAIT(0); }
        __syncthreads();
        if (it + 2 < NIT) load_stage(it + 2);

        const __half* as = smh + (it % 3) * (2*STG_H);
        const __half* bs = as + STG_H;
#pragma unroll
        for (int ks = 0; ks < 4; ks++) {          // 4 x k16
            uint32_t af[4][4];
#pragma unroll
            for (int mi = 0; mi < 4; mi++) {
                int rr = arow + mi * 16;
                af[mi][0] = *(const uint32_t*)&as[(rr     )*SROWH + ks*16 + kq2    ];
                af[mi][1] = *(const uint32_t*)&as[(rr +  8)*SROWH + ks*16 + kq2    ];
                af[mi][2] = *(const uint32_t*)&as[(rr     )*SROWH + ks*16 + 8 + kq2];
                af[mi][3] = *(const uint32_t*)&as[(rr +  8)*SROWH + ks*16 + 8 + kq2];
            }
            uint32_t bf[4][2];
#pragma unroll
            for (int ni = 0; ni < 4; ni++) {
                int cc = bcol + ni * 8;
                bf[ni][0] = *(const uint32_t*)&bs[cc*SROWH + ks*16 + kq2    ];
                bf[ni][1] = *(const uint32_t*)&bs[cc*SROWH + ks*16 + 8 + kq2];
            }
#pragma unroll
            for (int mi = 0; mi < 4; mi++)
#pragma unroll
                for (int ni = 0; ni < 4; ni++)
                    mma16816(acc[mi][ni], af[mi], bf[ni][0], bf[ni][1]);
        }
    }

    const float esc = (mode == 1 && z == 0) ? 0.125f : 1.0f;
#pragma unroll
    for (int mi = 0; mi < 4; mi++) {
        const int r_lo = row0 + wm * 64 + mi * 16 + (lane >> 2);
        const int r_hi = r_lo + 8;
#pragma unroll
        for (int ni = 0; ni < 4; ni++) {
            const int n = col0 + wn * 32 + ni * 8 + (lane & 3) * 2;
            const float2 bv = *(const float2*)(bia + n);
            float lx = (acc[mi][ni][0] + bv.x) * esc;
            float ly = (acc[mi][ni][1] + bv.y) * esc;
            float hx = (acc[mi][ni][2] + bv.x) * esc;
            float hy = (acc[mi][ni][3] + bv.y) * esc;
            if (mode == 0) {
                float* Cf = (float*)C;
                *(float2*)(Cf + (size_t)r_lo * DM + n) = make_float2(lx, ly);
                *(float2*)(Cf + (size_t)r_hi * DM + n) = make_float2(hx, hy);
            } else {
                __half* Ch = (__half*)C;
                const int h = n >> 6, dk = n & (DK - 1);
                const int bb_lo = r_lo >> 11, t_lo = r_lo & (T - 1);
                const int bb_hi = r_hi >> 11, t_hi = r_hi & (T - 1);
                if (z == 2) {
                    // V transposed: (b,h,d,t)
                    size_t base_lo = ((size_t)(bb_lo*NH + h)*DK);
                    size_t base_hi = ((size_t)(bb_hi*NH + h)*DK);
                    Ch[(base_lo + dk    )*T + t_lo] = __float2half_rn(lx);
                    Ch[(base_lo + dk + 1)*T + t_lo] = __float2half_rn(ly);
                    Ch[(base_hi + dk    )*T + t_hi] = __float2half_rn(hx);
                    Ch[(base_hi + dk + 1)*T + t_hi] = __float2half_rn(hy);
                } else {
                    __half2 lo = __floats2half2_rn(lx, ly);
                    __half2 hi = __floats2half2_rn(hx, hy);
                    *(__half2*)(Ch + (((size_t)(bb_lo*NH + h))*T + t_lo)*DK + dk) = lo;
                    *(__half2*)(Ch + (((size_t)(bb_hi*NH + h))*T + t_hi)*DK + dk) = hi;
                }
            }
        }
    }
}

// ---------------- fp16 tensor-core flash attention ---------------------------
// Q pre-scaled 1/8. K (b,h,t,d), V transposed (b,h,d,t). 3-stage KV ring.
#define FSTR 72                       // halves per row in smem tiles
#define KBYTESH (64*FSTR*2)           // 9216
#define BUFH (2*KBYTESH)              // 18432 per stage (K + Vt)
#define FA_SMEM (3*BUFH)              // 55296
#define NT_TILES (T/64)               // 32

__global__ __launch_bounds__(256, 2)
void flash_h(const __half* __restrict__ Q, const __half* __restrict__ K,
             const __half* __restrict__ Vt, const int* __restrict__ mask,
             __half* __restrict__ O) {
    extern __shared__ __half pool[];
    const int tid = threadIdx.x, wid = tid >> 5, lane = tid & 31;
    const int qt = blockIdx.x, h = blockIdx.y, b = blockIdx.z;
    const int bh = b*NH + h;
    const int r = lane >> 2, qd2 = (lane & 3) * 2;
    const int anyz = g_anyzero;
    const uint32_t pbase = smem_u32(pool);

    // ---- stage Q (128 x 64 halves) into stage-0 region, build fragments ----
    {
        const __half* Qg = Q + ((size_t)bh*T + (size_t)qt*128)*DK;
#pragma unroll
        for (int i = 0; i < 4; i++) {
            int e = tid + i*256;             // 1024 chunks
            int row = e >> 3, c8 = (e & 7) * 8;
            CP_ASYNC16(pbase + (uint32_t)(row*FSTR + c8)*2, Qg + row*DK + c8);
        }
        CP_COMMIT(); CP_WAIT(0);
    }
    __syncthreads();
    uint32_t qf[4][4];
    {
        const int r0 = wid*16 + r;
#pragma unroll
        for (int ks = 0; ks < 4; ks++) {
            qf[ks][0] = *(const uint32_t*)&pool[(r0    )*FSTR + ks*16 + qd2    ];
            qf[ks][1] = *(const uint32_t*)&pool[(r0 + 8)*FSTR + ks*16 + qd2    ];
            qf[ks][2] = *(const uint32_t*)&pool[(r0    )*FSTR + ks*16 + 8 + qd2];
            qf[ks][3] = *(const uint32_t*)&pool[(r0 + 8)*FSTR + ks*16 + 8 + qd2];
        }
    }
    __syncthreads();

    const __half* Kg  = K  + (size_t)bh*T*DK;
    const __half* Vtg = Vt + (size_t)bh*DK*T;

    auto loadKV = [&](int kt) {
        uint32_t kb = pbase + (uint32_t)(kt % 3) * BUFH;
        uint32_t vb = kb + KBYTESH;
        const __half* kg = Kg + (size_t)kt*64*DK;
#pragma unroll
        for (int i = 0; i < 4; i++) {
            int e = tid + i*256;             // 1024 chunks: 512 K + 512 Vt
            if (e < 512) {
                int row = e >> 3, c8 = (e & 7) * 8;
                CP_ASYNC16(kb + (uint32_t)(row*FSTR + c8)*2, kg + row*DK + c8);
            } else {
                int e2 = e - 512;
                int d = e2 >> 3, c8 = (e2 & 7) * 8;     // d row, key offset
                CP_ASYNC16(vb + (uint32_t)(d*FSTR + c8)*2,
                           Vtg + (size_t)d*T + kt*64 + c8);
            }
        }
        CP_COMMIT();
    };

    float m_lo = -1e30f, m_hi = -1e30f, l_lo = 0.f, l_hi = 0.f;
    float oacc[8][4];
#pragma unroll
    for (int i = 0; i < 8; i++)
#pragma unroll
        for (int j = 0; j < 4; j++) oacc[i][j] = 0.f;

    const int q0 = qt*128 + wid*16;

    loadKV(0);
    loadKV(1);

    for (int kt = 0; kt < NT_TILES; kt++) {
        if (kt + 1 < NT_TILES) { CP_WAIT(1); } else { CP_WAIT(0); }
        __syncthreads();
        if (kt + 2 < NT_TILES) loadKV(kt + 2);

        const __half* ksm = pool + (kt % 3) * (BUFH/2);
        const __half* vsm = ksm + (KBYTESH/2);

        // ---- S = Q K^T ----
        float sa[8][4];
#pragma unroll
        for (int i = 0; i < 8; i++)
#pragma unroll
            for (int j = 0; j < 4; j++) sa[i][j] = 0.f;
#pragma unroll
        for (int ks = 0; ks < 4; ks++) {
#pragma unroll
            for (int nt = 0; nt < 8; nt++) {
                uint32_t b0 = *(const uint32_t*)&ksm[(nt*8 + r)*FSTR + ks*16 + qd2    ];
                uint32_t b1 = *(const uint32_t*)&ksm[(nt*8 + r)*FSTR + ks*16 + 8 + qd2];
                mma16816(sa[nt], qf[ks], b0, b1);
            }
        }

        if (anyz) {
#pragma unroll
            for (int nt = 0; nt < 8; nt++) {
                const int col = kt*64 + nt*8 + qd2;
                int2 mlo = *(const int2*)(mask + (size_t)(q0 + r    )*T + col);
                int2 mhi = *(const int2*)(mask + (size_t)(q0 + r + 8)*T + col);
                if (mlo.x == 0) sa[nt][0] = -1e9f;
                if (mlo.y == 0) sa[nt][1] = -1e9f;
                if (mhi.x == 0) sa[nt][2] = -1e9f;
                if (mhi.y == 0) sa[nt][3] = -1e9f;
            }
        }

        // ---- online softmax ----
        float tm_lo = m_lo, tm_hi = m_hi;
#pragma unroll
        for (int nt = 0; nt < 8; nt++) {
            tm_lo = fmaxf(tm_lo, fmaxf(sa[nt][0], sa[nt][1]));
            tm_hi = fmaxf(tm_hi, fmaxf(sa[nt][2], sa[nt][3]));
        }
        tm_lo = fmaxf(tm_lo, __shfl_xor_sync(0xffffffffu, tm_lo, 1));
        tm_lo = fmaxf(tm_lo, __shfl_xor_sync(0xffffffffu, tm_lo, 2));
        tm_hi = fmaxf(tm_hi, __shfl_xor_sync(0xffffffffu, tm_hi, 1));
        tm_hi = fmaxf(tm_hi, __shfl_xor_sync(0xffffffffu, tm_hi, 2));
        const float corr_lo = __expf(m_lo - tm_lo);
        const float corr_hi = __expf(m_hi - tm_hi);
        m_lo = tm_lo; m_hi = tm_hi;

        float suml_lo = 0.f, suml_hi = 0.f;
#pragma unroll
        for (int nt = 0; nt < 8; nt++) {
            sa[nt][0] = __expf(sa[nt][0] - m_lo);
            sa[nt][1] = __expf(sa[nt][1] - m_lo);
            sa[nt][2] = __expf(sa[nt][2] - m_hi);
            sa[nt][3] = __expf(sa[nt][3] - m_hi);
            suml_lo += sa[nt][0] + sa[nt][1];
            suml_hi += sa[nt][2] + sa[nt][3];
        }
        suml_lo += __shfl_xor_sync(0xffffffffu, suml_lo, 1);
        suml_lo += __shfl_xor_sync(0xffffffffu, suml_lo, 2);
        suml_hi += __shfl_xor_sync(0xffffffffu, suml_hi, 1);
        suml_hi += __shfl_xor_sync(0xffffffffu, suml_hi, 2);
        l_lo = l_lo * corr_lo + suml_lo;
        l_hi = l_hi * corr_hi + suml_hi;
#pragma unroll
        for (int nt = 0; nt < 8; nt++) {
            oacc[nt][0] *= corr_lo; oacc[nt][1] *= corr_lo;
            oacc[nt][2] *= corr_hi; oacc[nt][3] *= corr_hi;
        }

        // ---- O += P V : C-frag(S) == A-frag(PV), lane-local repack ----
#pragma unroll
        for (int s = 0; s < 4; s++) {
            uint32_t ap[4];
            ap[0] = packh2(sa[2*s  ][0], sa[2*s  ][1]);
            ap[1] = packh2(sa[2*s  ][2], sa[2*s  ][3]);
            ap[2] = packh2(sa[2*s+1][0], sa[2*s+1][1]);
            ap[3] = packh2(sa[2*s+1][2], sa[2*s+1][3]);
#pragma unroll
            for (int nt = 0; nt < 8; nt++) {
                uint32_t b0 = *(const uint32_t*)&vsm[(nt*8 + r)*FSTR + s*16 + qd2    ];
                uint32_t b1 = *(const uint32_t*)&vsm[(nt*8 + r)*FSTR + s*16 + 8 + qd2];
                mma16816(oacc[nt], ap, b0, b1);
            }
        }
    }

    // ---- epilogue: O -> (b, t, h*64+d) fp16 ----
    const float ilo = 1.f / l_lo;
    const float ihi = 1.f / l_hi;
#pragma unroll
    for (int nt = 0; nt < 8; nt++) {
        const int col = h*64 + nt*8 + qd2;
        __half2 lo = __floats2half2_rn(oacc[nt][0]*ilo, oacc[nt][1]*ilo);
        __half2 hi = __floats2half2_rn(oacc[nt][2]*ihi, oacc[nt][3]*ihi);
        *(__half2*)(O + (size_t)(b*T + q0 + r    )*DM + col) = lo;
        *(__half2*)(O + (size_t)(b*T + q0 + r + 8)*DM + col) = hi;
    }
}

// ---------------- launch ----------------
extern "C" void kernel_launch(void* const* d_in, const int* in_sizes, int n_in,
                              void* d_out, int out_size) {
    const float* q    = (const float*)d_in[0];
    const float* k    = (const float*)d_in[1];
    const float* v    = (const float*)d_in[2];
    const int*   mask = (const int*)  d_in[3];
    const float* Wq = (const float*)d_in[4],  *bq = (const float*)d_in[5];
    const float* Aq = (const float*)d_in[6],  *Bq = (const float*)d_in[7];
    const float* Wk = (const float*)d_in[8],  *bk = (const float*)d_in[9];
    const float* Ak = (const float*)d_in[10], *Bk = (const float*)d_in[11];
    const float* Wv = (const float*)d_in[12], *bv = (const float*)d_in[13];
    const float* Av = (const float*)d_in[14], *Bv = (const float*)d_in[15];
    const float* Wo = (const float*)d_in[16], *bo = (const float*)d_in[17];
    float* out = (float*)d_out;

    __half *weffh, *woh, *acth, *Qh, *Kh, *Vth, *attnh;
    cudaGetSymbolAddress((void**)&weffh, g_weffh);
    cudaGetSymbolAddress((void**)&woh,   g_woh);
    cudaGetSymbolAddress((void**)&acth,  g_acth);
    cudaGetSymbolAddress((void**)&Qh,    g_q);
    cudaGetSymbolAddress((void**)&Kh,    g_k);
    cudaGetSymbolAddress((void**)&Vth,   g_vt);
    cudaGetSymbolAddress((void**)&attnh, g_attnh);

    __half* weffq = weffh;
    __half* weffk = weffh + (size_t)DM*DM;
    __half* weffv = weffh + (size_t)2*DM*DM;
    __half* aq = acth;
    __half* ak = acth + (size_t)MTOT*DM;
    __half* av = acth + (size_t)2*MTOT*DM;

    cudaFuncSetAttribute(gemm_h, cudaFuncAttributeMaxDynamicSharedMemorySize, GEMM_SMEM);
    cudaFuncSetAttribute(flash_h, cudaFuncAttributeMaxDynamicSharedMemorySize, FA_SMEM);

    act_half<<<dim3(MTOT*DM/8/256, 3), 256>>>(q, k, v, acth);
    prep_kernel<<<dim3(DM*DM/256, 4), 256>>>(Wq, Aq, Bq, Wk, Ak, Bk, Wv, Av, Bv,
                                             Wo, weffh, woh);
    maskscan_init<<<1, 1>>>();
    maskscan<<<4096, 256>>>(mask, T*T);

    dim3 gqkv(DM/128, MTOT/128, 3);     // 8 x 32 x 3
    gemm_h<<<gqkv, 256, GEMM_SMEM>>>(aq, ak, av, weffq, weffk, weffv,
                                     bq, bk, bv, Qh, Kh, Vth, 1);

    flash_h<<<dim3(T/128, NH, BATCH), 256, FA_SMEM>>>(Qh, Kh, Vth, mask, attnh);

    dim3 go(DM/128, MTOT/128, 1);
    gemm_h<<<go, 256, GEMM_SMEM>>>(attnh, attnh, attnh, woh, woh, woh,
                                   bo, bo, bo, out, out, out, 0);
}

// round 9
// speedup vs baseline: 1.9397x; 1.0051x over previous
#include <cuda_runtime.h>
#include <cuda_fp16.h>
#include <math.h>
#include <stdint.h>

#define BATCH 2
#define T 2048
#define DM 1024
#define NH 16
#define DK 64
#define RR 8
#define LORA_SCALE 2.0f
#define MTOT (BATCH*T)      // 4096

// ---------------- scratch ----------------
__device__ __half g_weffh[3][DM*DM];
__device__ __half g_woh[DM*DM];
__device__ __half g_acth[3][MTOT*DM];
__device__ __half g_q[BATCH*NH*T*DK];         // Q (b,h,t,d), pre-scaled 1/8
__device__ __half g_k[BATCH*NH*T*DK];         // K (b,h,t,d)
__device__ __half g_vt[BATCH*NH*DK*T];        // V transposed (b,h,d,t)
__device__ __half g_attnh[MTOT*DM];
__device__ int    g_anyzero;

// ---------------- helpers ----------------
#define CP_ASYNC16(dst, src) \
    asm volatile("cp.async.cg.shared.global [%0], [%1], 16;" :: "r"(dst), "l"(src))
#define CP_COMMIT() asm volatile("cp.async.commit_group;" ::: "memory")
#define CP_WAIT(n)  asm volatile("cp.async.wait_group %0;" :: "n"(n) : "memory")

__device__ __forceinline__ uint32_t smem_u32(const void* p) {
    uint32_t a;
    asm("{ .reg .u64 t; cvta.to.shared.u64 t, %1; cvt.u32.u64 %0, t; }" : "=r"(a) : "l"(p));
    return a;
}
__device__ __forceinline__ uint32_t packh2(float a, float b) {
    __half2 h = __floats2half2_rn(a, b);
    return *(uint32_t*)&h;
}
__device__ __forceinline__ void mma16816(float* c, const uint32_t* a,
                                         uint32_t b0, uint32_t b1) {
    asm volatile(
        "mma.sync.aligned.m16n8k16.row.col.f32.f16.f16.f32 "
        "{%0,%1,%2,%3}, {%4,%5,%6,%7}, {%8,%9}, {%0,%1,%2,%3};"
        : "+f"(c[0]), "+f"(c[1]), "+f"(c[2]), "+f"(c[3])
        : "r"(a[0]), "r"(a[1]), "r"(a[2]), "r"(a[3]), "r"(b0), "r"(b1));
}
__device__ __forceinline__ void ldsm4(uint32_t* r, uint32_t addr) {
    asm volatile("ldmatrix.sync.aligned.m8n8.x4.shared.b16 {%0,%1,%2,%3}, [%4];"
                 : "=r"(r[0]), "=r"(r[1]), "=r"(r[2]), "=r"(r[3]) : "r"(addr));
}

// ---------------- mask scan (int4) ----------------
__global__ void maskscan_init() { g_anyzero = 0; }
__global__ void maskscan(const int4* __restrict__ mask, int n4) {
    int i = blockIdx.x * 256 + threadIdx.x;
    int z = 0;
    for (int k = i; k < n4; k += gridDim.x * 256) {
        int4 m = mask[k];
        z |= (m.x == 0) | (m.y == 0) | (m.z == 0) | (m.w == 0);
    }
    if (__any_sync(0xffffffffu, z) && (threadIdx.x & 31) == 0)
        atomicOr(&g_anyzero, 1);
}

// ---------------- prep: weff q/k/v fp16 (z=0..2) + Wo fp16 (z=3) ------------
__global__ void prep_kernel(const float* __restrict__ Wq, const float* __restrict__ Aq,
                            const float* __restrict__ Bq,
                            const float* __restrict__ Wk, const float* __restrict__ Ak,
                            const float* __restrict__ Bk,
                            const float* __restrict__ Wv, const float* __restrict__ Av,
                            const float* __restrict__ Bv,
                            const float* __restrict__ Wo,
                            __half* __restrict__ weff, __half* __restrict__ wo) {
    const int z = blockIdx.y;
    int idx = blockIdx.x * 256 + threadIdx.x;
    if (z == 3) {
        wo[idx] = __float2half_rn(Wo[idx]);
        return;
    }
    const float* W = (z == 0) ? Wq : (z == 1) ? Wk : Wv;
    const float* A = (z == 0) ? Aq : (z == 1) ? Ak : Av;
    const float* B = (z == 0) ? Bq : (z == 1) ? Bk : Bv;
    int o = idx >> 10;
    int d = idx & 1023;
    float s = 0.f;
#pragma unroll
    for (int r = 0; r < RR; r++) s += B[o*RR + r] * A[r*DM + d];
    weff[(size_t)z*DM*DM + idx] = __float2half_rn(W[idx] + LORA_SCALE * s);
}

// ---------------- activations fp32 -> fp16 ----------------
__global__ void act_half(const float* __restrict__ q, const float* __restrict__ k,
                         const float* __restrict__ v, __half* __restrict__ out) {
    const int z = blockIdx.y;
    const float* src = (z == 0) ? q : (z == 1) ? k : v;
    int i = blockIdx.x * 256 + threadIdx.x;
    float4 a = ((const float4*)src)[i*2];
    float4 b = ((const float4*)src)[i*2 + 1];
    uint4 o;
    o.x = packh2(a.x, a.y); o.y = packh2(a.z, a.w);
    o.z = packh2(b.x, b.y); o.w = packh2(b.z, b.w);
    ((uint4*)(out + (size_t)z*MTOT*DM))[i] = o;
}

// ---------------- fp16 mma GEMM with ldmatrix --------------------------------
#define KT 64
#define NIT (DM / KT)          // 16
#define SROWH 72               // halves per row (64 + 8 pad), 144B (16B mult)
#define STG_H (128 * SROWH)
#define GEMM_SMEM (3 * 2 * STG_H * 2)   // 110592 B

__global__ __launch_bounds__(256, 2)
void gemm_h(const __half* __restrict__ A0, const __half* __restrict__ A1,
            const __half* __restrict__ A2,
            const __half* __restrict__ W0, const __half* __restrict__ W1,
            const __half* __restrict__ W2,
            const float* __restrict__ b0, const float* __restrict__ b1,
            const float* __restrict__ b2,
            void* __restrict__ C0, void* __restrict__ C1,
            void* __restrict__ C2, int mode) {
    extern __shared__ __half smh[];
    const int z = blockIdx.z;
    const __half* A   = (z == 0) ? A0 : (z == 1) ? A1 : A2;
    const __half* W   = (z == 0) ? W0 : (z == 1) ? W1 : W2;
    const float*  bia = (z == 0) ? b0 : (z == 1) ? b1 : b2;
    void*         C   = (z == 0) ? C0 : (z == 1) ? C1 : C2;

    const int tid = threadIdx.x;
    const int wid = tid >> 5;
    const int lane = tid & 31;
    const int wm = wid >> 2;
    const int wn = wid & 3;
    const int row0 = blockIdx.y * 128;
    const int col0 = blockIdx.x * 128;
    const uint32_t sbase = smem_u32(smh);

    // ldmatrix per-lane offsets (bytes): row = base + (lane&15), koff = (lane>>4)*8
    const uint32_t a_off = ((uint32_t)(wm*64 + (lane & 15)) * SROWH + (lane >> 4) * 8) * 2;
    const uint32_t b_off = ((uint32_t)(wn*32 + (lane & 15)) * SROWH + (lane >> 4) * 8) * 2;

    float acc[4][4][4];
#pragma unroll
    for (int i = 0; i < 4; i++)
#pragma unroll
        for (int j = 0; j < 4; j++)
#pragma unroll
            for (int r = 0; r < 4; r++) acc[i][j][r] = 0.f;

    auto load_stage = [&](int g) {
        const int st = g % 3;
        const int k0 = g * KT;
        const uint32_t abase = sbase + (uint32_t)st * (2*STG_H*2);
        const uint32_t bbase = abase + STG_H*2;
#pragma unroll
        for (int i = 0; i < 4; i++) {
            int e = tid + i * 256;
            int r = e >> 3;
            int c8 = (e & 7) * 8;
            uint32_t doff = (uint32_t)(r * SROWH + c8) * 2;
            CP_ASYNC16(abase + doff, A + (size_t)(row0 + r) * DM + k0 + c8);
            CP_ASYNC16(bbase + doff, W + (size_t)(col0 + r) * DM + k0 + c8);
        }
        CP_COMMIT();
    };

    load_stage(0);
    load_stage(1);

    for (int it = 0; it < NIT; it++) {
        if (it + 1 < NIT) { CP_WAIT(1); } else { CP_WAIT(0); }
        __syncthreads();
        if (it + 2 < NIT) load_stage(it + 2);

        const uint32_t abase = sbase + (uint32_t)(it % 3) * (2*STG_H*2) + a_off;
        const uint32_t bbase = sbase + (uint32_t)(it % 3) * (2*STG_H*2) + STG_H*2 + b_off;
#pragma unroll
        for (int ks = 0; ks < 4; ks++) {          // 4 x k16
            uint32_t af[4][4];
#pragma unroll
            for (int mi = 0; mi < 4; mi++)
                ldsm4(af[mi], abase + (uint32_t)mi * (16*SROWH*2) + ks*32);
#pragma unroll
            for (int p = 0; p < 2; p++) {          // ni pairs {0,1},{2,3}
                uint32_t bf[4];
                ldsm4(bf, bbase + (uint32_t)p * (16*SROWH*2) + ks*32);
#pragma unroll
                for (int mi = 0; mi < 4; mi++) {
                    mma16816(acc[mi][2*p    ], af[mi], bf[0], bf[2]);
                    mma16816(acc[mi][2*p + 1], af[mi], bf[1], bf[3]);
                }
            }
        }
    }

    const float esc = (mode == 1 && z == 0) ? 0.125f : 1.0f;
#pragma unroll
    for (int mi = 0; mi < 4; mi++) {
        const int r_lo = row0 + wm * 64 + mi * 16 + (lane >> 2);
        const int r_hi = r_lo + 8;
#pragma unroll
        for (int ni = 0; ni < 4; ni++) {
            const int n = col0 + wn * 32 + ni * 8 + (lane & 3) * 2;
            const float2 bv = *(const float2*)(bia + n);
            float lx = (acc[mi][ni][0] + bv.x) * esc;
            float ly = (acc[mi][ni][1] + bv.y) * esc;
            float hx = (acc[mi][ni][2] + bv.x) * esc;
            float hy = (acc[mi][ni][3] + bv.y) * esc;
            if (mode == 0) {
                float* Cf = (float*)C;
                *(float2*)(Cf + (size_t)r_lo * DM + n) = make_float2(lx, ly);
                *(float2*)(Cf + (size_t)r_hi * DM + n) = make_float2(hx, hy);
            } else {
                __half* Ch = (__half*)C;
                const int h = n >> 6, dk = n & (DK - 1);
                const int bb_lo = r_lo >> 11, t_lo = r_lo & (T - 1);
                const int bb_hi = r_hi >> 11, t_hi = r_hi & (T - 1);
                if (z == 2) {
                    size_t base_lo = ((size_t)(bb_lo*NH + h)*DK);
                    size_t base_hi = ((size_t)(bb_hi*NH + h)*DK);
                    Ch[(base_lo + dk    )*T + t_lo] = __float2half_rn(lx);
                    Ch[(base_lo + dk + 1)*T + t_lo] = __float2half_rn(ly);
                    Ch[(base_hi + dk    )*T + t_hi] = __float2half_rn(hx);
                    Ch[(base_hi + dk + 1)*T + t_hi] = __float2half_rn(hy);
                } else {
                    __half2 lo = __floats2half2_rn(lx, ly);
                    __half2 hi = __floats2half2_rn(hx, hy);
                    *(__half2*)(Ch + (((size_t)(bb_lo*NH + h))*T + t_lo)*DK + dk) = lo;
                    *(__half2*)(Ch + (((size_t)(bb_hi*NH + h))*T + t_hi)*DK + dk) = hi;
                }
            }
        }
    }
}

// ---------------- fp16 flash attention with ldmatrix -------------------------
#define FSTR 72
#define KBYTESH (64*FSTR*2)           // 9216
#define BUFH (2*KBYTESH)              // 18432 per stage
#define FA_SMEM (3*BUFH)              // 55296
#define NT_TILES (T/64)               // 32

__global__ __launch_bounds__(256, 2)
void flash_h(const __half* __restrict__ Q, const __half* __restrict__ K,
             const __half* __restrict__ Vt, const int* __restrict__ mask,
             __half* __restrict__ O) {
    extern __shared__ __half pool[];
    const int tid = threadIdx.x, wid = tid >> 5, lane = tid & 31;
    const int qt = blockIdx.x, h = blockIdx.y, b = blockIdx.z;
    const int bh = b*NH + h;
    const int r = lane >> 2, qd2 = (lane & 3) * 2;
    const int anyz = g_anyzero;
    const uint32_t pbase = smem_u32(pool);

    // ldmatrix per-lane offsets
    const uint32_t q_off = ((uint32_t)(wid*16 + (lane & 15)) * FSTR + (lane >> 4) * 8) * 2;
    const uint32_t kv_off = ((uint32_t)(lane & 15) * FSTR + (lane >> 4) * 8) * 2;

    // ---- stage Q, build fragments ----
    {
        const __half* Qg = Q + ((size_t)bh*T + (size_t)qt*128)*DK;
#pragma unroll
        for (int i = 0; i < 4; i++) {
            int e = tid + i*256;
            int row = e >> 3, c8 = (e & 7) * 8;
            CP_ASYNC16(pbase + (uint32_t)(row*FSTR + c8)*2, Qg + row*DK + c8);
        }
        CP_COMMIT(); CP_WAIT(0);
    }
    __syncthreads();
    uint32_t qf[4][4];
#pragma unroll
    for (int ks = 0; ks < 4; ks++)
        ldsm4(qf[ks], pbase + q_off + ks*32);
    __syncthreads();

    const __half* Kg  = K  + (size_t)bh*T*DK;
    const __half* Vtg = Vt + (size_t)bh*DK*T;

    auto loadKV = [&](int kt) {
        uint32_t kb = pbase + (uint32_t)(kt % 3) * BUFH;
        uint32_t vb = kb + KBYTESH;
        const __half* kg = Kg + (size_t)kt*64*DK;
#pragma unroll
        for (int i = 0; i < 4; i++) {
            int e = tid + i*256;
            if (e < 512) {
                int row = e >> 3, c8 = (e & 7) * 8;
                CP_ASYNC16(kb + (uint32_t)(row*FSTR + c8)*2, kg + row*DK + c8);
            } else {
                int e2 = e - 512;
                int d = e2 >> 3, c8 = (e2 & 7) * 8;
                CP_ASYNC16(vb + (uint32_t)(d*FSTR + c8)*2,
                           Vtg + (size_t)d*T + kt*64 + c8);
            }
        }
        CP_COMMIT();
    };

    float m_lo = -1e30f, m_hi = -1e30f, l_lo = 0.f, l_hi = 0.f;
    float oacc[8][4];
#pragma unroll
    for (int i = 0; i < 8; i++)
#pragma unroll
        for (int j = 0; j < 4; j++) oacc[i][j] = 0.f;

    const int q0 = qt*128 + wid*16;

    loadKV(0);
    loadKV(1);

    for (int kt = 0; kt < NT_TILES; kt++) {
        if (kt + 1 < NT_TILES) { CP_WAIT(1); } else { CP_WAIT(0); }
        __syncthreads();
        if (kt + 2 < NT_TILES) loadKV(kt + 2);

        const uint32_t ksmb = pbase + (uint32_t)(kt % 3) * BUFH + kv_off;
        const uint32_t vsmb = ksmb + KBYTESH;

        // ---- S = Q K^T ----
        float sa[8][4];
#pragma unroll
        for (int i = 0; i < 8; i++)
#pragma unroll
            for (int j = 0; j < 4; j++) sa[i][j] = 0.f;
#pragma unroll
        for (int ks = 0; ks < 4; ks++) {
#pragma unroll
            for (int p = 0; p < 4; p++) {          // nt pairs
                uint32_t kf[4];
                ldsm4(kf, ksmb + (uint32_t)p * (16*FSTR*2) + ks*32);
                mma16816(sa[2*p    ], qf[ks], kf[0], kf[2]);
                mma16816(sa[2*p + 1], qf[ks], kf[1], kf[3]);
            }
        }

        if (anyz) {
#pragma unroll
            for (int nt = 0; nt < 8; nt++) {
                const int col = kt*64 + nt*8 + qd2;
                int2 mlo = *(const int2*)(mask + (size_t)(q0 + r    )*T + col);
                int2 mhi = *(const int2*)(mask + (size_t)(q0 + r + 8)*T + col);
                if (mlo.x == 0) sa[nt][0] = -1e9f;
                if (mlo.y == 0) sa[nt][1] = -1e9f;
                if (mhi.x == 0) sa[nt][2] = -1e9f;
                if (mhi.y == 0) sa[nt][3] = -1e9f;
            }
        }

        // ---- online softmax ----
        float tm_lo = m_lo, tm_hi = m_hi;
#pragma unroll
        for (int nt = 0; nt < 8; nt++) {
            tm_lo = fmaxf(tm_lo, fmaxf(sa[nt][0], sa[nt][1]));
            tm_hi = fmaxf(tm_hi, fmaxf(sa[nt][2], sa[nt][3]));
        }
        tm_lo = fmaxf(tm_lo, __shfl_xor_sync(0xffffffffu, tm_lo, 1));
        tm_lo = fmaxf(tm_lo, __shfl_xor_sync(0xffffffffu, tm_lo, 2));
        tm_hi = fmaxf(tm_hi, __shfl_xor_sync(0xffffffffu, tm_hi, 1));
        tm_hi = fmaxf(tm_hi, __shfl_xor_sync(0xffffffffu, tm_hi, 2));
        const float corr_lo = __expf(m_lo - tm_lo);
        const float corr_hi = __expf(m_hi - tm_hi);
        m_lo = tm_lo; m_hi = tm_hi;

        float suml_lo = 0.f, suml_hi = 0.f;
#pragma unroll
        for (int nt = 0; nt < 8; nt++) {
            sa[nt][0] = __expf(sa[nt][0] - m_lo);
            sa[nt][1] = __expf(sa[nt][1] - m_lo);
            sa[nt][2] = __expf(sa[nt][2] - m_hi);
            sa[nt][3] = __expf(sa[nt][3] - m_hi);
            suml_lo += sa[nt][0] + sa[nt][1];
            suml_hi += sa[nt][2] + sa[nt][3];
        }
        suml_lo += __shfl_xor_sync(0xffffffffu, suml_lo, 1);
        suml_lo += __shfl_xor_sync(0xffffffffu, suml_lo, 2);
        suml_hi += __shfl_xor_sync(0xffffffffu, suml_hi, 1);
        suml_hi += __shfl_xor_sync(0xffffffffu, suml_hi, 2);
        l_lo = l_lo * corr_lo + suml_lo;
        l_hi = l_hi * corr_hi + suml_hi;
#pragma unroll
        for (int nt = 0; nt < 8; nt++) {
            oacc[nt][0] *= corr_lo; oacc[nt][1] *= corr_lo;
            oacc[nt][2] *= corr_hi; oacc[nt][3] *= corr_hi;
        }

        // ---- O += P V ----
#pragma unroll
        for (int s = 0; s < 4; s++) {
            uint32_t ap[4];
            ap[0] = packh2(sa[2*s  ][0], sa[2*s  ][1]);
            ap[1] = packh2(sa[2*s  ][2], sa[2*s  ][3]);
            ap[2] = packh2(sa[2*s+1][0], sa[2*s+1][1]);
            ap[3] = packh2(sa[2*s+1][2], sa[2*s+1][3]);
#pragma unroll
            for (int p = 0; p < 4; p++) {          // d pairs
                uint32_t vf[4];
                ldsm4(vf, vsmb + (uint32_t)p * (16*FSTR*2) + s*32);
                mma16816(oacc[2*p    ], ap, vf[0], vf[2]);
                mma16816(oacc[2*p + 1], ap, vf[1], vf[3]);
            }
        }
    }

    // ---- epilogue ----
    const float ilo = 1.f / l_lo;
    const float ihi = 1.f / l_hi;
#pragma unroll
    for (int nt = 0; nt < 8; nt++) {
        const int col = h*64 + nt*8 + qd2;
        __half2 lo = __floats2half2_rn(oacc[nt][0]*ilo, oacc[nt][1]*ilo);
        __half2 hi = __floats2half2_rn(oacc[nt][2]*ihi, oacc[nt][3]*ihi);
        *(__half2*)(O + (size_t)(b*T + q0 + r    )*DM + col) = lo;
        *(__half2*)(O + (size_t)(b*T + q0 + r + 8)*DM + col) = hi;
    }
}

// ---------------- launch ----------------
extern "C" void kernel_launch(void* const* d_in, const int* in_sizes, int n_in,
                              void* d_out, int out_size) {
    const float* q    = (const float*)d_in[0];
    const float* k    = (const float*)d_in[1];
    const float* v    = (const float*)d_in[2];
    const int*   mask = (const int*)  d_in[3];
    const float* Wq = (const float*)d_in[4],  *bq = (const float*)d_in[5];
    const float* Aq = (const float*)d_in[6],  *Bq = (const float*)d_in[7];
    const float* Wk = (const float*)d_in[8],  *bk = (const float*)d_in[9];
    const float* Ak = (const float*)d_in[10], *Bk = (const float*)d_in[11];
    const float* Wv = (const float*)d_in[12], *bv = (const float*)d_in[13];
    const float* Av = (const float*)d_in[14], *Bv = (const float*)d_in[15];
    const float* Wo = (const float*)d_in[16], *bo = (const float*)d_in[17];
    float* out = (float*)d_out;

    __half *weffh, *woh, *acth, *Qh, *Kh, *Vth, *attnh;
    cudaGetSymbolAddress((void**)&weffh, g_weffh);
    cudaGetSymbolAddress((void**)&woh,   g_woh);
    cudaGetSymbolAddress((void**)&acth,  g_acth);
    cudaGetSymbolAddress((void**)&Qh,    g_q);
    cudaGetSymbolAddress((void**)&Kh,    g_k);
    cudaGetSymbolAddress((void**)&Vth,   g_vt);
    cudaGetSymbolAddress((void**)&attnh, g_attnh);

    __half* weffq = weffh;
    __half* weffk = weffh + (size_t)DM*DM;
    __half* weffv = weffh + (size_t)2*DM*DM;
    __half* aq = acth;
    __half* ak = acth + (size_t)MTOT*DM;
    __half* av = acth + (size_t)2*MTOT*DM;

    cudaFuncSetAttribute(gemm_h, cudaFuncAttributeMaxDynamicSharedMemorySize, GEMM_SMEM);
    cudaFuncSetAttribute(flash_h, cudaFuncAttributeMaxDynamicSharedMemorySize, FA_SMEM);

    act_half<<<dim3(MTOT*DM/8/256, 3), 256>>>(q, k, v, acth);
    prep_kernel<<<dim3(DM*DM/256, 4), 256>>>(Wq, Aq, Bq, Wk, Ak, Bk, Wv, Av, Bv,
                                             Wo, weffh, woh);
    maskscan_init<<<1, 1>>>();
    maskscan<<<1024, 256>>>((const int4*)mask, T*T/4);

    dim3 gqkv(DM/128, MTOT/128, 3);
    gemm_h<<<gqkv, 256, GEMM_SMEM>>>(aq, ak, av, weffq, weffk, weffv,
                                     bq, bk, bv, Qh, Kh, Vth, 1);

    flash_h<<<dim3(T/128, NH, BATCH), 256, FA_SMEM>>>(Qh, Kh, Vth, mask, attnh);

    dim3 go(DM/128, MTOT/128, 1);
    gemm_h<<<go, 256, GEMM_SMEM>>>(attnh, attnh, attnh, woh, woh, woh,
                                   bo, bo, bo, out, out, out, 0);
}

// round 10
// speedup vs baseline: 1.9915x; 1.0267x over previous
#include <cuda_runtime.h>
#include <cuda_fp16.h>
#include <math.h>
#include <stdint.h>

#define BATCH 2
#define T 2048
#define DM 1024
#define NH 16
#define DK 64
#define RR 8
#define LORA_SCALE 2.0f
#define MTOT (BATCH*T)      // 4096

// ---------------- scratch ----------------
__device__ __half g_weffh[3][DM*DM];
__device__ __half g_woh[DM*DM];
__device__ __half g_acth[3][MTOT*DM];
__device__ __half g_q[BATCH*NH*T*DK];         // Q (b,h,t,d), pre-scaled 1/8
__device__ __half g_k[BATCH*NH*T*DK];         // K (b,h,t,d)
__device__ __half g_vt[BATCH*NH*DK*T];        // V transposed (b,h,d,t)
__device__ __half g_attnh[MTOT*DM];
__device__ int    g_anyzero;                  // monotonic OR; static 0

// ---------------- helpers ----------------
#define CP_ASYNC16(dst, src) \
    asm volatile("cp.async.cg.shared.global [%0], [%1], 16;" :: "r"(dst), "l"(src))
#define CP_COMMIT() asm volatile("cp.async.commit_group;" ::: "memory")
#define CP_WAIT(n)  asm volatile("cp.async.wait_group %0;" :: "n"(n) : "memory")

__device__ __forceinline__ uint32_t smem_u32(const void* p) {
    uint32_t a;
    asm("{ .reg .u64 t; cvta.to.shared.u64 t, %1; cvt.u32.u64 %0, t; }" : "=r"(a) : "l"(p));
    return a;
}
__device__ __forceinline__ uint32_t packh2(float a, float b) {
    __half2 h = __floats2half2_rn(a, b);
    return *(uint32_t*)&h;
}
__device__ __forceinline__ void mma16816(float* c, const uint32_t* a,
                                         uint32_t b0, uint32_t b1) {
    asm volatile(
        "mma.sync.aligned.m16n8k16.row.col.f32.f16.f16.f32 "
        "{%0,%1,%2,%3}, {%4,%5,%6,%7}, {%8,%9}, {%0,%1,%2,%3};"
        : "+f"(c[0]), "+f"(c[1]), "+f"(c[2]), "+f"(c[3])
        : "r"(a[0]), "r"(a[1]), "r"(a[2]), "r"(a[3]), "r"(b0), "r"(b1));
}
__device__ __forceinline__ void ldsm4(uint32_t* r, uint32_t addr) {
    asm volatile("ldmatrix.sync.aligned.m8n8.x4.shared.b16 {%0,%1,%2,%3}, [%4];"
                 : "=r"(r[0]), "=r"(r[1]), "=r"(r[2]), "=r"(r[3]) : "r"(addr));
}

// ---------------- fused prep ----------------
// blocks [0,6144): act fp32->fp16 (z = bx>>11)
// blocks [6144,22528): weff z=0..2 / wo z=3 ((bx-6144)>>12)
// blocks [22528,23552): maskscan (int4)
#define PREP_BLOCKS 23552

__global__ void prep_fused(const float* __restrict__ q, const float* __restrict__ k,
                           const float* __restrict__ v,
                           const float* __restrict__ Wq, const float* __restrict__ Aq,
                           const float* __restrict__ Bq,
                           const float* __restrict__ Wk, const float* __restrict__ Ak,
                           const float* __restrict__ Bk,
                           const float* __restrict__ Wv, const float* __restrict__ Av,
                           const float* __restrict__ Bv,
                           const float* __restrict__ Wo,
                           const int4* __restrict__ mask4,
                           __half* __restrict__ acth,
                           __half* __restrict__ weff, __half* __restrict__ wo) {
    const int bx = blockIdx.x;
    if (bx < 6144) {
        const int z = bx >> 11;
        const int i = (bx & 2047) * 256 + threadIdx.x;      // uint4 index
        const float* src = (z == 0) ? q : (z == 1) ? k : v;
        float4 a = ((const float4*)src)[i*2];
        float4 b = ((const float4*)src)[i*2 + 1];
        uint4 o;
        o.x = packh2(a.x, a.y); o.y = packh2(a.z, a.w);
        o.z = packh2(b.x, b.y); o.w = packh2(b.z, b.w);
        ((uint4*)(acth + (size_t)z*MTOT*DM))[i] = o;
    } else if (bx < 22528) {
        const int t = bx - 6144;
        const int z = t >> 12;
        const int idx = (t & 4095) * 256 + threadIdx.x;
        if (z == 3) {
            wo[idx] = __float2half_rn(Wo[idx]);
            return;
        }
        const float* W = (z == 0) ? Wq : (z == 1) ? Wk : Wv;
        const float* A = (z == 0) ? Aq : (z == 1) ? Ak : Av;
        const float* B = (z == 0) ? Bq : (z == 1) ? Bk : Bv;
        int o = idx >> 10;
        int d = idx & 1023;
        float s = 0.f;
#pragma unroll
        for (int r = 0; r < RR; r++) s += B[o*RR + r] * A[r*DM + d];
        weff[(size_t)z*DM*DM + idx] = __float2half_rn(W[idx] + LORA_SCALE * s);
    } else {
        const int i = (bx - 22528) * 256 + threadIdx.x;     // 0..262143
        int z = 0;
        for (int k4 = i; k4 < T*T/4; k4 += 262144) {
            int4 m = mask4[k4];
            z |= (m.x == 0) | (m.y == 0) | (m.z == 0) | (m.w == 0);
        }
        if (__any_sync(0xffffffffu, z) && (threadIdx.x & 31) == 0)
            atomicOr(&g_anyzero, 1);
    }
}

// ---------------- fp16 mma GEMM with ldmatrix (unchanged inner) --------------
#define KT 64
#define NIT (DM / KT)          // 16
#define SROWH 72               // halves per row (64 + 8 pad)
#define STG_H (128 * SROWH)
#define GEMM_SMEM (3 * 2 * STG_H * 2)   // 110592 B

__global__ __launch_bounds__(256, 2)
void gemm_h(const __half* __restrict__ A0, const __half* __restrict__ A1,
            const __half* __restrict__ A2,
            const __half* __restrict__ W0, const __half* __restrict__ W1,
            const __half* __restrict__ W2,
            const float* __restrict__ b0, const float* __restrict__ b1,
            const float* __restrict__ b2,
            void* __restrict__ C0, void* __restrict__ C1,
            void* __restrict__ C2, int mode) {
    extern __shared__ __half smh[];
    const int z = blockIdx.z;
    const __half* A   = (z == 0) ? A0 : (z == 1) ? A1 : A2;
    const __half* W   = (z == 0) ? W0 : (z == 1) ? W1 : W2;
    const float*  bia = (z == 0) ? b0 : (z == 1) ? b1 : b2;
    void*         C   = (z == 0) ? C0 : (z == 1) ? C1 : C2;

    const int tid = threadIdx.x;
    const int wid = tid >> 5;
    const int lane = tid & 31;
    const int wm = wid >> 2;
    const int wn = wid & 3;
    const int row0 = blockIdx.y * 128;
    const int col0 = blockIdx.x * 128;
    const uint32_t sbase = smem_u32(smh);

    const uint32_t a_off = ((uint32_t)(wm*64 + (lane & 15)) * SROWH + (lane >> 4) * 8) * 2;
    const uint32_t b_off = ((uint32_t)(wn*32 + (lane & 15)) * SROWH + (lane >> 4) * 8) * 2;

    float acc[4][4][4];
#pragma unroll
    for (int i = 0; i < 4; i++)
#pragma unroll
        for (int j = 0; j < 4; j++)
#pragma unroll
            for (int r = 0; r < 4; r++) acc[i][j][r] = 0.f;

    auto load_stage = [&](int g) {
        const int st = g % 3;
        const int k0 = g * KT;
        const uint32_t abase = sbase + (uint32_t)st * (2*STG_H*2);
        const uint32_t bbase = abase + STG_H*2;
#pragma unroll
        for (int i = 0; i < 4; i++) {
            int e = tid + i * 256;
            int r = e >> 3;
            int c8 = (e & 7) * 8;
            uint32_t doff = (uint32_t)(r * SROWH + c8) * 2;
            CP_ASYNC16(abase + doff, A + (size_t)(row0 + r) * DM + k0 + c8);
            CP_ASYNC16(bbase + doff, W + (size_t)(col0 + r) * DM + k0 + c8);
        }
        CP_COMMIT();
    };

    load_stage(0);
    load_stage(1);

    for (int it = 0; it < NIT; it++) {
        if (it + 1 < NIT) { CP_WAIT(1); } else { CP_WAIT(0); }
        __syncthreads();
        if (it + 2 < NIT) load_stage(it + 2);

        const uint32_t abase = sbase + (uint32_t)(it % 3) * (2*STG_H*2) + a_off;
        const uint32_t bbase = sbase + (uint32_t)(it % 3) * (2*STG_H*2) + STG_H*2 + b_off;
#pragma unroll
        for (int ks = 0; ks < 4; ks++) {
            uint32_t af[4][4];
#pragma unroll
            for (int mi = 0; mi < 4; mi++)
                ldsm4(af[mi], abase + (uint32_t)mi * (16*SROWH*2) + ks*32);
#pragma unroll
            for (int p = 0; p < 2; p++) {
                uint32_t bf[4];
                ldsm4(bf, bbase + (uint32_t)p * (16*SROWH*2) + ks*32);
#pragma unroll
                for (int mi = 0; mi < 4; mi++) {
                    mma16816(acc[mi][2*p    ], af[mi], bf[0], bf[2]);
                    mma16816(acc[mi][2*p + 1], af[mi], bf[1], bf[3]);
                }
            }
        }
    }

    const float esc = (mode == 1 && z == 0) ? 0.125f : 1.0f;
#pragma unroll
    for (int mi = 0; mi < 4; mi++) {
        const int r_lo = row0 + wm * 64 + mi * 16 + (lane >> 2);
        const int r_hi = r_lo + 8;
#pragma unroll
        for (int ni = 0; ni < 4; ni++) {
            const int n = col0 + wn * 32 + ni * 8 + (lane & 3) * 2;
            const float2 bv = *(const float2*)(bia + n);
            float lx = (acc[mi][ni][0] + bv.x) * esc;
            float ly = (acc[mi][ni][1] + bv.y) * esc;
            float hx = (acc[mi][ni][2] + bv.x) * esc;
            float hy = (acc[mi][ni][3] + bv.y) * esc;
            if (mode == 0) {
                float* Cf = (float*)C;
                *(float2*)(Cf + (size_t)r_lo * DM + n) = make_float2(lx, ly);
                *(float2*)(Cf + (size_t)r_hi * DM + n) = make_float2(hx, hy);
            } else {
                __half* Ch = (__half*)C;
                const int h = n >> 6, dk = n & (DK - 1);
                const int bb_lo = r_lo >> 11, t_lo = r_lo & (T - 1);
                const int bb_hi = r_hi >> 11, t_hi = r_hi & (T - 1);
                if (z == 2) {
                    size_t base_lo = ((size_t)(bb_lo*NH + h)*DK);
                    size_t base_hi = ((size_t)(bb_hi*NH + h)*DK);
                    Ch[(base_lo + dk    )*T + t_lo] = __float2half_rn(lx);
                    Ch[(base_lo + dk + 1)*T + t_lo] = __float2half_rn(ly);
                    Ch[(base_hi + dk    )*T + t_hi] = __float2half_rn(hx);
                    Ch[(base_hi + dk + 1)*T + t_hi] = __float2half_rn(hy);
                } else {
                    __half2 lo = __floats2half2_rn(lx, ly);
                    __half2 hi = __floats2half2_rn(hx, hy);
                    *(__half2*)(Ch + (((size_t)(bb_lo*NH + h))*T + t_lo)*DK + dk) = lo;
                    *(__half2*)(Ch + (((size_t)(bb_hi*NH + h))*T + t_hi)*DK + dk) = hi;
                }
            }
        }
    }
}

// ---------------- fp16 flash attention: 512 thr, 256 q rows/CTA --------------
#define FSTR 72
#define KBYTESH (64*FSTR*2)           // 9216
#define BUFH (2*KBYTESH)              // 18432 per stage
#define FA_SMEM (3*BUFH)              // 55296
#define NT_TILES (T/64)               // 32

__global__ __launch_bounds__(512)
void flash_h(const __half* __restrict__ Q, const __half* __restrict__ K,
             const __half* __restrict__ Vt, const int* __restrict__ mask,
             __half* __restrict__ O) {
    extern __shared__ __half pool[];
    const int tid = threadIdx.x, wid = tid >> 5, lane = tid & 31;
    const int qt = blockIdx.x, h = blockIdx.y, b = blockIdx.z;
    const int bh = b*NH + h;
    const int r = lane >> 2, qd2 = (lane & 3) * 2;
    const int anyz = g_anyzero;
    const uint32_t pbase = smem_u32(pool);

    const uint32_t q_off = ((uint32_t)(wid*16 + (lane & 15)) * FSTR + (lane >> 4) * 8) * 2;
    const uint32_t kv_off = ((uint32_t)(lane & 15) * FSTR + (lane >> 4) * 8) * 2;

    // ---- stage Q (256 x 64 halves into stages 0..1), build fragments ----
    {
        const __half* Qg = Q + ((size_t)bh*T + (size_t)qt*256)*DK;
#pragma unroll
        for (int i = 0; i < 4; i++) {
            int e = tid + i*512;             // 2048 chunks
            int row = e >> 3, c8 = (e & 7) * 8;
            CP_ASYNC16(pbase + (uint32_t)(row*FSTR + c8)*2, Qg + row*DK + c8);
        }
        CP_COMMIT(); CP_WAIT(0);
    }
    __syncthreads();
    uint32_t qf[4][4];
#pragma unroll
    for (int ks = 0; ks < 4; ks++)
        ldsm4(qf[ks], pbase + q_off + ks*32);
    __syncthreads();

    const __half* Kg  = K  + (size_t)bh*T*DK;
    const __half* Vtg = Vt + (size_t)bh*DK*T;

    auto loadKV = [&](int kt) {
        uint32_t kb = pbase + (uint32_t)(kt % 3) * BUFH;
        uint32_t vb = kb + KBYTESH;
        const __half* kg = Kg + (size_t)kt*64*DK;
#pragma unroll
        for (int i = 0; i < 2; i++) {
            int e = tid + i*512;             // 1024 chunks: 512 K + 512 Vt
            if (e < 512) {
                int row = e >> 3, c8 = (e & 7) * 8;
                CP_ASYNC16(kb + (uint32_t)(row*FSTR + c8)*2, kg + row*DK + c8);
            } else {
                int e2 = e - 512;
                int d = e2 >> 3, c8 = (e2 & 7) * 8;
                CP_ASYNC16(vb + (uint32_t)(d*FSTR + c8)*2,
                           Vtg + (size_t)d*T + kt*64 + c8);
            }
        }
        CP_COMMIT();
    };

    float m_lo = -1e30f, m_hi = -1e30f, l_lo = 0.f, l_hi = 0.f;
    float oacc[8][4];
#pragma unroll
    for (int i = 0; i < 8; i++)
#pragma unroll
        for (int j = 0; j < 4; j++) oacc[i][j] = 0.f;

    const int q0 = qt*256 + wid*16;

    loadKV(0);
    loadKV(1);

    for (int kt = 0; kt < NT_TILES; kt++) {
        if (kt + 1 < NT_TILES) { CP_WAIT(1); } else { CP_WAIT(0); }
        __syncthreads();
        if (kt + 2 < NT_TILES) loadKV(kt + 2);

        const uint32_t ksmb = pbase + (uint32_t)(kt % 3) * BUFH + kv_off;
        const uint32_t vsmb = ksmb + KBYTESH;

        // ---- S = Q K^T ----
        float sa[8][4];
#pragma unroll
        for (int i = 0; i < 8; i++)
#pragma unroll
            for (int j = 0; j < 4; j++) sa[i][j] = 0.f;
#pragma unroll
        for (int ks = 0; ks < 4; ks++) {
#pragma unroll
            for (int p = 0; p < 4; p++) {
                uint32_t kf[4];
                ldsm4(kf, ksmb + (uint32_t)p * (16*FSTR*2) + ks*32);
                mma16816(sa[2*p    ], qf[ks], kf[0], kf[2]);
                mma16816(sa[2*p + 1], qf[ks], kf[1], kf[3]);
            }
        }

        if (anyz) {
#pragma unroll
            for (int nt = 0; nt < 8; nt++) {
                const int col = kt*64 + nt*8 + qd2;
                int2 mlo = *(const int2*)(mask + (size_t)(q0 + r    )*T + col);
                int2 mhi = *(const int2*)(mask + (size_t)(q0 + r + 8)*T + col);
                if (mlo.x == 0) sa[nt][0] = -1e9f;
                if (mlo.y == 0) sa[nt][1] = -1e9f;
                if (mhi.x == 0) sa[nt][2] = -1e9f;
                if (mhi.y == 0) sa[nt][3] = -1e9f;
            }
        }

        // ---- online softmax ----
        float tm_lo = m_lo, tm_hi = m_hi;
#pragma unroll
        for (int nt = 0; nt < 8; nt++) {
            tm_lo = fmaxf(tm_lo, fmaxf(sa[nt][0], sa[nt][1]));
            tm_hi = fmaxf(tm_hi, fmaxf(sa[nt][2], sa[nt][3]));
        }
        tm_lo = fmaxf(tm_lo, __shfl_xor_sync(0xffffffffu, tm_lo, 1));
        tm_lo = fmaxf(tm_lo, __shfl_xor_sync(0xffffffffu, tm_lo, 2));
        tm_hi = fmaxf(tm_hi, __shfl_xor_sync(0xffffffffu, tm_hi, 1));
        tm_hi = fmaxf(tm_hi, __shfl_xor_sync(0xffffffffu, tm_hi, 2));
        const float corr_lo = __expf(m_lo - tm_lo);
        const float corr_hi = __expf(m_hi - tm_hi);
        m_lo = tm_lo; m_hi = tm_hi;

        float suml_lo = 0.f, suml_hi = 0.f;
#pragma unroll
        for (int nt = 0; nt < 8; nt++) {
            sa[nt][0] = __expf(sa[nt][0] - m_lo);
            sa[nt][1] = __expf(sa[nt][1] - m_lo);
            sa[nt][2] = __expf(sa[nt][2] - m_hi);
            sa[nt][3] = __expf(sa[nt][3] - m_hi);
            suml_lo += sa[nt][0] + sa[nt][1];
            suml_hi += sa[nt][2] + sa[nt][3];
        }
        suml_lo += __shfl_xor_sync(0xffffffffu, suml_lo, 1);
        suml_lo += __shfl_xor_sync(0xffffffffu, suml_lo, 2);
        suml_hi += __shfl_xor_sync(0xffffffffu, suml_hi, 1);
        suml_hi += __shfl_xor_sync(0xffffffffu, suml_hi, 2);
        l_lo = l_lo * corr_lo + suml_lo;
        l_hi = l_hi * corr_hi + suml_hi;
#pragma unroll
        for (int nt = 0; nt < 8; nt++) {
            oacc[nt][0] *= corr_lo; oacc[nt][1] *= corr_lo;
            oacc[nt][2] *= corr_hi; oacc[nt][3] *= corr_hi;
        }

        // ---- O += P V ----
#pragma unroll
        for (int s = 0; s < 4; s++) {
            uint32_t ap[4];
            ap[0] = packh2(sa[2*s  ][0], sa[2*s  ][1]);
            ap[1] = packh2(sa[2*s  ][2], sa[2*s  ][3]);
            ap[2] = packh2(sa[2*s+1][0], sa[2*s+1][1]);
            ap[3] = packh2(sa[2*s+1][2], sa[2*s+1][3]);
#pragma unroll
            for (int p = 0; p < 4; p++) {
                uint32_t vf[4];
                ldsm4(vf, vsmb + (uint32_t)p * (16*FSTR*2) + s*32);
                mma16816(oacc[2*p    ], ap, vf[0], vf[2]);
                mma16816(oacc[2*p + 1], ap, vf[1], vf[3]);
            }
        }
    }

    // ---- epilogue ----
    const float ilo = 1.f / l_lo;
    const float ihi = 1.f / l_hi;
#pragma unroll
    for (int nt = 0; nt < 8; nt++) {
        const int col = h*64 + nt*8 + qd2;
        __half2 lo = __floats2half2_rn(oacc[nt][0]*ilo, oacc[nt][1]*ilo);
        __half2 hi = __floats2half2_rn(oacc[nt][2]*ihi, oacc[nt][3]*ihi);
        *(__half2*)(O + (size_t)(b*T + q0 + r    )*DM + col) = lo;
        *(__half2*)(O + (size_t)(b*T + q0 + r + 8)*DM + col) = hi;
    }
}

// ---------------- launch ----------------
extern "C" void kernel_launch(void* const* d_in, const int* in_sizes, int n_in,
                              void* d_out, int out_size) {
    const float* q    = (const float*)d_in[0];
    const float* k    = (const float*)d_in[1];
    const float* v    = (const float*)d_in[2];
    const int*   mask = (const int*)  d_in[3];
    const float* Wq = (const float*)d_in[4],  *bq = (const float*)d_in[5];
    const float* Aq = (const float*)d_in[6],  *Bq = (const float*)d_in[7];
    const float* Wk = (const float*)d_in[8],  *bk = (const float*)d_in[9];
    const float* Ak = (const float*)d_in[10], *Bk = (const float*)d_in[11];
    const float* Wv = (const float*)d_in[12], *bv = (const float*)d_in[13];
    const float* Av = (const float*)d_in[14], *Bv = (const float*)d_in[15];
    const float* Wo = (const float*)d_in[16], *bo = (const float*)d_in[17];
    float* out = (float*)d_out;

    __half *weffh, *woh, *acth, *Qh, *Kh, *Vth, *attnh;
    cudaGetSymbolAddress((void**)&weffh, g_weffh);
    cudaGetSymbolAddress((void**)&woh,   g_woh);
    cudaGetSymbolAddress((void**)&acth,  g_acth);
    cudaGetSymbolAddress((void**)&Qh,    g_q);
    cudaGetSymbolAddress((void**)&Kh,    g_k);
    cudaGetSymbolAddress((void**)&Vth,   g_vt);
    cudaGetSymbolAddress((void**)&attnh, g_attnh);

    __half* weffq = weffh;
    __half* weffk = weffh + (size_t)DM*DM;
    __half* weffv = weffh + (size_t)2*DM*DM;
    __half* aq = acth;
    __half* ak = acth + (size_t)MTOT*DM;
    __half* av = acth + (size_t)2*MTOT*DM;

    cudaFuncSetAttribute(gemm_h, cudaFuncAttributeMaxDynamicSharedMemorySize, GEMM_SMEM);
    cudaFuncSetAttribute(flash_h, cudaFuncAttributeMaxDynamicSharedMemorySize, FA_SMEM);

    prep_fused<<<PREP_BLOCKS, 256>>>(q, k, v, Wq, Aq, Bq, Wk, Ak, Bk,
                                     Wv, Av, Bv, Wo, (const int4*)mask,
                                     acth, weffh, woh);

    dim3 gqkv(DM/128, MTOT/128, 3);
    gemm_h<<<gqkv, 256, GEMM_SMEM>>>(aq, ak, av, weffq, weffk, weffv,
                                     bq, bk, bv, Qh, Kh, Vth, 1);

    flash_h<<<dim3(T/256, NH, BATCH), 512, FA_SMEM>>>(Qh, Kh, Vth, mask, attnh);

    dim3 go(DM/128, MTOT/128, 1);
    gemm_h<<<go, 256, GEMM_SMEM>>>(attnh, attnh, attnh, woh, woh, woh,
                                   bo, bo, bo, out, out, out, 0);
}

// round 11
// speedup vs baseline: 2.0610x; 1.0349x over previous
#include <cuda_runtime.h>
#include <cuda_fp16.h>
#include <math.h>
#include <stdint.h>

#define BATCH 2
#define T 2048
#define DM 1024
#define NH 16
#define DK 64
#define RR 8
#define LORA_SCALE 2.0f
#define MTOT (BATCH*T)      // 4096
#define LOG2E 1.44269504088896f

// ---------------- scratch ----------------
__device__ __half g_weffh[3][DM*DM];
__device__ __half g_woh[DM*DM];
__device__ __half g_acth[3][MTOT*DM];
__device__ __half g_q[BATCH*NH*T*DK];         // Q (b,h,t,d), pre-scaled (1/8)*log2e
__device__ __half g_k[BATCH*NH*T*DK];         // K (b,h,t,d)
__device__ __half g_vt[BATCH*NH*DK*T];        // V transposed (b,h,d,t)
__device__ __half g_attnh[MTOT*DM];
__device__ int    g_anyzero;                  // monotonic OR; static 0

// ---------------- helpers ----------------
#define CP_ASYNC16(dst, src) \
    asm volatile("cp.async.cg.shared.global [%0], [%1], 16;" :: "r"(dst), "l"(src))
#define CP_COMMIT() asm volatile("cp.async.commit_group;" ::: "memory")
#define CP_WAIT(n)  asm volatile("cp.async.wait_group %0;" :: "n"(n) : "memory")

__device__ __forceinline__ uint32_t smem_u32(const void* p) {
    uint32_t a;
    asm("{ .reg .u64 t; cvta.to.shared.u64 t, %1; cvt.u32.u64 %0, t; }" : "=r"(a) : "l"(p));
    return a;
}
__device__ __forceinline__ uint32_t packh2(float a, float b) {
    __half2 h = __floats2half2_rn(a, b);
    return *(uint32_t*)&h;
}
__device__ __forceinline__ float ex2f(float x) {
    float r;
    asm("ex2.approx.f32 %0, %1;" : "=f"(r) : "f"(x));
    return r;
}
__device__ __forceinline__ uint32_t h2ex2(uint32_t x) {
    uint32_t r;
    asm("ex2.approx.f16x2 %0, %1;" : "=r"(r) : "r"(x));
    return r;
}
__device__ __forceinline__ void mma16816(float* c, const uint32_t* a,
                                         uint32_t b0, uint32_t b1) {
    asm volatile(
        "mma.sync.aligned.m16n8k16.row.col.f32.f16.f16.f32 "
        "{%0,%1,%2,%3}, {%4,%5,%6,%7}, {%8,%9}, {%0,%1,%2,%3};"
        : "+f"(c[0]), "+f"(c[1]), "+f"(c[2]), "+f"(c[3])
        : "r"(a[0]), "r"(a[1]), "r"(a[2]), "r"(a[3]), "r"(b0), "r"(b1));
}
__device__ __forceinline__ void ldsm4(uint32_t* r, uint32_t addr) {
    asm volatile("ldmatrix.sync.aligned.m8n8.x4.shared.b16 {%0,%1,%2,%3}, [%4];"
                 : "=r"(r[0]), "=r"(r[1]), "=r"(r[2]), "=r"(r[3]) : "r"(addr));
}

// ---------------- fused prep ----------------
#define PREP_BLOCKS 23552

__global__ void prep_fused(const float* __restrict__ q, const float* __restrict__ k,
                           const float* __restrict__ v,
                           const float* __restrict__ Wq, const float* __restrict__ Aq,
                           const float* __restrict__ Bq,
                           const float* __restrict__ Wk, const float* __restrict__ Ak,
                           const float* __restrict__ Bk,
                           const float* __restrict__ Wv, const float* __restrict__ Av,
                           const float* __restrict__ Bv,
                           const float* __restrict__ Wo,
                           const int4* __restrict__ mask4,
                           __half* __restrict__ acth,
                           __half* __restrict__ weff, __half* __restrict__ wo) {
    const int bx = blockIdx.x;
    if (bx < 6144) {
        const int z = bx >> 11;
        const int i = (bx & 2047) * 256 + threadIdx.x;
        const float* src = (z == 0) ? q : (z == 1) ? k : v;
        float4 a = ((const float4*)src)[i*2];
        float4 b = ((const float4*)src)[i*2 + 1];
        uint4 o;
        o.x = packh2(a.x, a.y); o.y = packh2(a.z, a.w);
        o.z = packh2(b.x, b.y); o.w = packh2(b.z, b.w);
        ((uint4*)(acth + (size_t)z*MTOT*DM))[i] = o;
    } else if (bx < 22528) {
        const int t = bx - 6144;
        const int z = t >> 12;
        const int idx = (t & 4095) * 256 + threadIdx.x;
        if (z == 3) {
            wo[idx] = __float2half_rn(Wo[idx]);
            return;
        }
        const float* W = (z == 0) ? Wq : (z == 1) ? Wk : Wv;
        const float* A = (z == 0) ? Aq : (z == 1) ? Ak : Av;
        const float* B = (z == 0) ? Bq : (z == 1) ? Bk : Bv;
        int o = idx >> 10;
        int d = idx & 1023;
        float s = 0.f;
#pragma unroll
        for (int r = 0; r < RR; r++) s += B[o*RR + r] * A[r*DM + d];
        weff[(size_t)z*DM*DM + idx] = __float2half_rn(W[idx] + LORA_SCALE * s);
    } else {
        const int i = (bx - 22528) * 256 + threadIdx.x;
        int z = 0;
        for (int k4 = i; k4 < T*T/4; k4 += 262144) {
            int4 m = mask4[k4];
            z |= (m.x == 0) | (m.y == 0) | (m.z == 0) | (m.w == 0);
        }
        if (__any_sync(0xffffffffu, z) && (threadIdx.x & 31) == 0)
            atomicOr(&g_anyzero, 1);
    }
}

// ---------------- fp16 mma GEMM with ldmatrix --------------------------------
#define KT 64
#define NIT (DM / KT)          // 16
#define SROWH 72
#define STG_H (128 * SROWH)
#define GEMM_SMEM (3 * 2 * STG_H * 2)   // 110592 B

__global__ __launch_bounds__(256, 2)
void gemm_h(const __half* __restrict__ A0, const __half* __restrict__ A1,
            const __half* __restrict__ A2,
            const __half* __restrict__ W0, const __half* __restrict__ W1,
            const __half* __restrict__ W2,
            const float* __restrict__ b0, const float* __restrict__ b1,
            const float* __restrict__ b2,
            void* __restrict__ C0, void* __restrict__ C1,
            void* __restrict__ C2, int mode) {
    extern __shared__ __half smh[];
    const int z = blockIdx.z;
    const __half* A   = (z == 0) ? A0 : (z == 1) ? A1 : A2;
    const __half* W   = (z == 0) ? W0 : (z == 1) ? W1 : W2;
    const float*  bia = (z == 0) ? b0 : (z == 1) ? b1 : b2;
    void*         C   = (z == 0) ? C0 : (z == 1) ? C1 : C2;

    const int tid = threadIdx.x;
    const int wid = tid >> 5;
    const int lane = tid & 31;
    const int wm = wid >> 2;
    const int wn = wid & 3;
    const int row0 = blockIdx.y * 128;
    const int col0 = blockIdx.x * 128;
    const uint32_t sbase = smem_u32(smh);

    const uint32_t a_off = ((uint32_t)(wm*64 + (lane & 15)) * SROWH + (lane >> 4) * 8) * 2;
    const uint32_t b_off = ((uint32_t)(wn*32 + (lane & 15)) * SROWH + (lane >> 4) * 8) * 2;

    float acc[4][4][4];
#pragma unroll
    for (int i = 0; i < 4; i++)
#pragma unroll
        for (int j = 0; j < 4; j++)
#pragma unroll
            for (int r = 0; r < 4; r++) acc[i][j][r] = 0.f;

    auto load_stage = [&](int g) {
        const int st = g % 3;
        const int k0 = g * KT;
        const uint32_t abase = sbase + (uint32_t)st * (2*STG_H*2);
        const uint32_t bbase = abase + STG_H*2;
#pragma unroll
        for (int i = 0; i < 4; i++) {
            int e = tid + i * 256;
            int r = e >> 3;
            int c8 = (e & 7) * 8;
            uint32_t doff = (uint32_t)(r * SROWH + c8) * 2;
            CP_ASYNC16(abase + doff, A + (size_t)(row0 + r) * DM + k0 + c8);
            CP_ASYNC16(bbase + doff, W + (size_t)(col0 + r) * DM + k0 + c8);
        }
        CP_COMMIT();
    };

    load_stage(0);
    load_stage(1);

    for (int it = 0; it < NIT; it++) {
        if (it + 1 < NIT) { CP_WAIT(1); } else { CP_WAIT(0); }
        __syncthreads();
        if (it + 2 < NIT) load_stage(it + 2);

        const uint32_t abase = sbase + (uint32_t)(it % 3) * (2*STG_H*2) + a_off;
        const uint32_t bbase = sbase + (uint32_t)(it % 3) * (2*STG_H*2) + STG_H*2 + b_off;
#pragma unroll
        for (int ks = 0; ks < 4; ks++) {
            uint32_t af[4][4];
#pragma unroll
            for (int mi = 0; mi < 4; mi++)
                ldsm4(af[mi], abase + (uint32_t)mi * (16*SROWH*2) + ks*32);
#pragma unroll
            for (int p = 0; p < 2; p++) {
                uint32_t bf[4];
                ldsm4(bf, bbase + (uint32_t)p * (16*SROWH*2) + ks*32);
#pragma unroll
                for (int mi = 0; mi < 4; mi++) {
                    mma16816(acc[mi][2*p    ], af[mi], bf[0], bf[2]);
                    mma16816(acc[mi][2*p + 1], af[mi], bf[1], bf[3]);
                }
            }
        }
    }

    // Q gets (1/8)*log2e so flash works in log2 domain
    const float esc = (mode == 1 && z == 0) ? (0.125f * LOG2E) : 1.0f;
#pragma unroll
    for (int mi = 0; mi < 4; mi++) {
        const int r_lo = row0 + wm * 64 + mi * 16 + (lane >> 2);
        const int r_hi = r_lo + 8;
#pragma unroll
        for (int ni = 0; ni < 4; ni++) {
            const int n = col0 + wn * 32 + ni * 8 + (lane & 3) * 2;
            const float2 bv = *(const float2*)(bia + n);
            float lx = (acc[mi][ni][0] + bv.x) * esc;
            float ly = (acc[mi][ni][1] + bv.y) * esc;
            float hx = (acc[mi][ni][2] + bv.x) * esc;
            float hy = (acc[mi][ni][3] + bv.y) * esc;
            if (mode == 0) {
                float* Cf = (float*)C;
                *(float2*)(Cf + (size_t)r_lo * DM + n) = make_float2(lx, ly);
                *(float2*)(Cf + (size_t)r_hi * DM + n) = make_float2(hx, hy);
            } else {
                __half* Ch = (__half*)C;
                const int h = n >> 6, dk = n & (DK - 1);
                const int bb_lo = r_lo >> 11, t_lo = r_lo & (T - 1);
                const int bb_hi = r_hi >> 11, t_hi = r_hi & (T - 1);
                if (z == 2) {
                    size_t base_lo = ((size_t)(bb_lo*NH + h)*DK);
                    size_t base_hi = ((size_t)(bb_hi*NH + h)*DK);
                    Ch[(base_lo + dk    )*T + t_lo] = __float2half_rn(lx);
                    Ch[(base_lo + dk + 1)*T + t_lo] = __float2half_rn(ly);
                    Ch[(base_hi + dk    )*T + t_hi] = __float2half_rn(hx);
                    Ch[(base_hi + dk + 1)*T + t_hi] = __float2half_rn(hy);
                } else {
                    __half2 lo = __floats2half2_rn(lx, ly);
                    __half2 hi = __floats2half2_rn(hx, hy);
                    *(__half2*)(Ch + (((size_t)(bb_lo*NH + h))*T + t_lo)*DK + dk) = lo;
                    *(__half2*)(Ch + (((size_t)(bb_hi*NH + h))*T + t_hi)*DK + dk) = hi;
                }
            }
        }
    }
}

// ---------------- fp16 flash attention: f16x2 exp + ones-MMA l ---------------
#define FSTR 72
#define KBYTESH (64*FSTR*2)           // 9216
#define BUFH (2*KBYTESH)              // 18432 per stage
#define FA_SMEM (3*BUFH)              // 55296
#define NT_TILES (T/64)               // 32
#define ONES2 0x3C003C00u             // half2(1,1)

__global__ __launch_bounds__(512)
void flash_h(const __half* __restrict__ Q, const __half* __restrict__ K,
             const __half* __restrict__ Vt, const int* __restrict__ mask,
             __half* __restrict__ O) {
    extern __shared__ __half pool[];
    const int tid = threadIdx.x, wid = tid >> 5, lane = tid & 31;
    const int qt = blockIdx.x, h = blockIdx.y, b = blockIdx.z;
    const int bh = b*NH + h;
    const int r = lane >> 2, qd2 = (lane & 3) * 2;
    const int anyz = g_anyzero;
    const uint32_t pbase = smem_u32(pool);

    const uint32_t q_off = ((uint32_t)(wid*16 + (lane & 15)) * FSTR + (lane >> 4) * 8) * 2;
    const uint32_t kv_off = ((uint32_t)(lane & 15) * FSTR + (lane >> 4) * 8) * 2;

    {
        const __half* Qg = Q + ((size_t)bh*T + (size_t)qt*256)*DK;
#pragma unroll
        for (int i = 0; i < 4; i++) {
            int e = tid + i*512;
            int row = e >> 3, c8 = (e & 7) * 8;
            CP_ASYNC16(pbase + (uint32_t)(row*FSTR + c8)*2, Qg + row*DK + c8);
        }
        CP_COMMIT(); CP_WAIT(0);
    }
    __syncthreads();
    uint32_t qf[4][4];
#pragma unroll
    for (int ks = 0; ks < 4; ks++)
        ldsm4(qf[ks], pbase + q_off + ks*32);
    __syncthreads();

    const __half* Kg  = K  + (size_t)bh*T*DK;
    const __half* Vtg = Vt + (size_t)bh*DK*T;

    auto loadKV = [&](int kt) {
        uint32_t kb = pbase + (uint32_t)(kt % 3) * BUFH;
        uint32_t vb = kb + KBYTESH;
        const __half* kg = Kg + (size_t)kt*64*DK;
#pragma unroll
        for (int i = 0; i < 2; i++) {
            int e = tid + i*512;
            if (e < 512) {
                int row = e >> 3, c8 = (e & 7) * 8;
                CP_ASYNC16(kb + (uint32_t)(row*FSTR + c8)*2, kg + row*DK + c8);
            } else {
                int e2 = e - 512;
                int d = e2 >> 3, c8 = (e2 & 7) * 8;
                CP_ASYNC16(vb + (uint32_t)(d*FSTR + c8)*2,
                           Vtg + (size_t)d*T + kt*64 + c8);
            }
        }
        CP_COMMIT();
    };

    float m_lo = -1e30f, m_hi = -1e30f;
    float oacc[8][4];
#pragma unroll
    for (int i = 0; i < 8; i++)
#pragma unroll
        for (int j = 0; j < 4; j++) oacc[i][j] = 0.f;
    float lacc[4] = {0.f, 0.f, 0.f, 0.f};

    const int q0 = qt*256 + wid*16;

    loadKV(0);
    loadKV(1);

    for (int kt = 0; kt < NT_TILES; kt++) {
        if (kt + 1 < NT_TILES) { CP_WAIT(1); } else { CP_WAIT(0); }
        __syncthreads();
        if (kt + 2 < NT_TILES) loadKV(kt + 2);

        const uint32_t ksmb = pbase + (uint32_t)(kt % 3) * BUFH + kv_off;
        const uint32_t vsmb = ksmb + KBYTESH;

        // ---- S = Q K^T  (log2 domain; Q pre-scaled by (1/8)*log2e) ----
        float sa[8][4];
#pragma unroll
        for (int i = 0; i < 8; i++)
#pragma unroll
            for (int j = 0; j < 4; j++) sa[i][j] = 0.f;
#pragma unroll
        for (int ks = 0; ks < 4; ks++) {
#pragma unroll
            for (int p = 0; p < 4; p++) {
                uint32_t kf[4];
                ldsm4(kf, ksmb + (uint32_t)p * (16*FSTR*2) + ks*32);
                mma16816(sa[2*p    ], qf[ks], kf[0], kf[2]);
                mma16816(sa[2*p + 1], qf[ks], kf[1], kf[3]);
            }
        }

        if (anyz) {
#pragma unroll
            for (int nt = 0; nt < 8; nt++) {
                const int col = kt*64 + nt*8 + qd2;
                int2 mlo = *(const int2*)(mask + (size_t)(q0 + r    )*T + col);
                int2 mhi = *(const int2*)(mask + (size_t)(q0 + r + 8)*T + col);
                if (mlo.x == 0) sa[nt][0] = -1e9f;
                if (mlo.y == 0) sa[nt][1] = -1e9f;
                if (mhi.x == 0) sa[nt][2] = -1e9f;
                if (mhi.y == 0) sa[nt][3] = -1e9f;
            }
        }

        // ---- online softmax (log2 domain) ----
        float tm_lo = m_lo, tm_hi = m_hi;
#pragma unroll
        for (int nt = 0; nt < 8; nt++) {
            tm_lo = fmaxf(tm_lo, fmaxf(sa[nt][0], sa[nt][1]));
            tm_hi = fmaxf(tm_hi, fmaxf(sa[nt][2], sa[nt][3]));
        }
        tm_lo = fmaxf(tm_lo, __shfl_xor_sync(0xffffffffu, tm_lo, 1));
        tm_lo = fmaxf(tm_lo, __shfl_xor_sync(0xffffffffu, tm_lo, 2));
        tm_hi = fmaxf(tm_hi, __shfl_xor_sync(0xffffffffu, tm_hi, 1));
        tm_hi = fmaxf(tm_hi, __shfl_xor_sync(0xffffffffu, tm_hi, 2));
        const float corr_lo = ex2f(m_lo - tm_lo);
        const float corr_hi = ex2f(m_hi - tm_hi);
        m_lo = tm_lo; m_hi = tm_hi;

        // ---- P = exp2(s - m) in fp16x2, directly A-fragment-ready ----
        uint32_t ph[8][2];
#pragma unroll
        for (int nt = 0; nt < 8; nt++) {
            ph[nt][0] = h2ex2(packh2(sa[nt][0] - m_lo, sa[nt][1] - m_lo));
            ph[nt][1] = h2ex2(packh2(sa[nt][2] - m_hi, sa[nt][3] - m_hi));
        }

        lacc[0] *= corr_lo; lacc[1] *= corr_lo;
        lacc[2] *= corr_hi; lacc[3] *= corr_hi;
#pragma unroll
        for (int nt = 0; nt < 8; nt++) {
            oacc[nt][0] *= corr_lo; oacc[nt][1] *= corr_lo;
            oacc[nt][2] *= corr_hi; oacc[nt][3] *= corr_hi;
        }

        // ---- O += P V ; l += P @ ones ----
#pragma unroll
        for (int s = 0; s < 4; s++) {
            uint32_t ap[4];
            ap[0] = ph[2*s  ][0];
            ap[1] = ph[2*s  ][1];
            ap[2] = ph[2*s+1][0];
            ap[3] = ph[2*s+1][1];
            mma16816(lacc, ap, ONES2, ONES2);
#pragma unroll
            for (int p = 0; p < 4; p++) {
                uint32_t vf[4];
                ldsm4(vf, vsmb + (uint32_t)p * (16*FSTR*2) + s*32);
                mma16816(oacc[2*p    ], ap, vf[0], vf[2]);
                mma16816(oacc[2*p + 1], ap, vf[1], vf[3]);
            }
        }
    }

    // ---- epilogue ----
    const float ilo = 1.f / lacc[0];
    const float ihi = 1.f / lacc[2];
#pragma unroll
    for (int nt = 0; nt < 8; nt++) {
        const int col = h*64 + nt*8 + qd2;
        __half2 lo = __floats2half2_rn(oacc[nt][0]*ilo, oacc[nt][1]*ilo);
        __half2 hi = __floats2half2_rn(oacc[nt][2]*ihi, oacc[nt][3]*ihi);
        *(__half2*)(O + (size_t)(b*T + q0 + r    )*DM + col) = lo;
        *(__half2*)(O + (size_t)(b*T + q0 + r + 8)*DM + col) = hi;
    }
}

// ---------------- launch ----------------
extern "C" void kernel_launch(void* const* d_in, const int* in_sizes, int n_in,
                              void* d_out, int out_size) {
    const float* q    = (const float*)d_in[0];
    const float* k    = (const float*)d_in[1];
    const float* v    = (const float*)d_in[2];
    const int*   mask = (const int*)  d_in[3];
    const float* Wq = (const float*)d_in[4],  *bq = (const float*)d_in[5];
    const float* Aq = (const float*)d_in[6],  *Bq = (const float*)d_in[7];
    const float* Wk = (const float*)d_in[8],  *bk = (const float*)d_in[9];
    const float* Ak = (const float*)d_in[10], *Bk = (const float*)d_in[11];
    const float* Wv = (const float*)d_in[12], *bv = (const float*)d_in[13];
    const float* Av = (const float*)d_in[14], *Bv = (const float*)d_in[15];
    const float* Wo = (const float*)d_in[16], *bo = (const float*)d_in[17];
    float* out = (float*)d_out;

    __half *weffh, *woh, *acth, *Qh, *Kh, *Vth, *attnh;
    cudaGetSymbolAddress((void**)&weffh, g_weffh);
    cudaGetSymbolAddress((void**)&woh,   g_woh);
    cudaGetSymbolAddress((void**)&acth,  g_acth);
    cudaGetSymbolAddress((void**)&Qh,    g_q);
    cudaGetSymbolAddress((void**)&Kh,    g_k);
    cudaGetSymbolAddress((void**)&Vth,   g_vt);
    cudaGetSymbolAddress((void**)&attnh, g_attnh);

    __half* weffq = weffh;
    __half* weffk = weffh + (size_t)DM*DM;
    __half* weffv = weffh + (size_t)2*DM*DM;
    __half* aq = acth;
    __half* ak = acth + (size_t)MTOT*DM;
    __half* av = acth + (size_t)2*MTOT*DM;

    cudaFuncSetAttribute(gemm_h, cudaFuncAttributeMaxDynamicSharedMemorySize, GEMM_SMEM);
    cudaFuncSetAttribute(flash_h, cudaFuncAttributeMaxDynamicSharedMemorySize, FA_SMEM);

    prep_fused<<<PREP_BLOCKS, 256>>>(q, k, v, Wq, Aq, Bq, Wk, Ak, Bk,
                                     Wv, Av, Bv, Wo, (const int4*)mask,
                                     acth, weffh, woh);

    dim3 gqkv(DM/128, MTOT/128, 3);
    gemm_h<<<gqkv, 256, GEMM_SMEM>>>(aq, ak, av, weffq, weffk, weffv,
                                     bq, bk, bv, Qh, Kh, Vth, 1);

    flash_h<<<dim3(T/256, NH, BATCH), 512, FA_SMEM>>>(Qh, Kh, Vth, mask, attnh);

    dim3 go(DM/128, MTOT/128, 1);
    gemm_h<<<go, 256, GEMM_SMEM>>>(attnh, attnh, attnh, woh, woh, woh,
                                   bo, bo, bo, out, out, out, 0);
}